// round 7
// baseline (speedup 1.0000x reference)
#include <cuda_runtime.h>

#define HH 16
#define NN 8192
#define DD 64
#define WW 128
#define TS 32
#define NEGINF (-1e30f)

typedef unsigned long long u64;

// Pooled K/V scratch (allocation-free: __device__ globals)
__device__ float g_k1[HH * 1024 * DD];
__device__ float g_v1[HH * 1024 * DD];
__device__ float g_k2[HH * 128 * DD];
__device__ float g_v2[HH * 128 * DD];
__device__ float g_k3[HH * 16 * DD];
__device__ float g_v3[HH * 16 * DD];

// ---------------- packed f32x2 helpers (Blackwell) ----------------
__device__ __forceinline__ void ffma2(u64& acc, u64 a, u64 b) {
    asm("fma.rn.f32x2 %0, %1, %2, %0;" : "+l"(acc) : "l"(a), "l"(b));
}
// acc = acc * a + b
__device__ __forceinline__ void fmul_add2(u64& acc, u64 a, u64 b) {
    asm("fma.rn.f32x2 %0, %0, %1, %2;" : "+l"(acc) : "l"(a), "l"(b));
}
__device__ __forceinline__ u64 mul2(u64 a, u64 b) {
    u64 r; asm("mul.rn.f32x2 %0, %1, %2;" : "=l"(r) : "l"(a), "l"(b)); return r;
}
__device__ __forceinline__ u64 pack2(float x) {
    u64 r; asm("mov.b64 %0, {%1, %1};" : "=l"(r) : "f"(x)); return r;
}
__device__ __forceinline__ float2 unpack2(u64 v) {
    float lo, hi; asm("mov.b64 {%0, %1}, %2;" : "=f"(lo), "=f"(hi) : "l"(v));
    return make_float2(lo, hi);
}

// ---------------- cp.async helpers ----------------
__device__ __forceinline__ void cp16(const void* smem_dst, const void* gsrc) {
    unsigned sa = (unsigned)__cvta_generic_to_shared(smem_dst);
    asm volatile("cp.async.cg.shared.global [%0], [%1], 16;" :: "r"(sa), "l"(gsrc));
}
__device__ __forceinline__ void cp_commit() {
    asm volatile("cp.async.commit_group;" ::: "memory");
}
__device__ __forceinline__ void cp_wait_all() {
    asm volatile("cp.async.wait_group 0;" ::: "memory");
}

// ---------------- pooling kernels ----------------
__global__ void pool1_kernel(const float* __restrict__ k, const float* __restrict__ v) {
    int idx = blockIdx.x * blockDim.x + threadIdx.x;
    if (idx >= HH * 1024 * DD) return;
    int dd = idx & (DD - 1);
    int c  = (idx / DD) & 1023;
    int h  = idx / (DD * 1024);
    const float* ks = k + ((size_t)h * NN + (size_t)c * 8) * DD + dd;
    const float* vs = v + ((size_t)h * NN + (size_t)c * 8) * DD + dd;
    float sk = 0.f, sv = 0.f;
#pragma unroll
    for (int r = 0; r < 8; r++) { sk += ks[r * DD]; sv += vs[r * DD]; }
    g_k1[idx] = sk * 0.125f;
    g_v1[idx] = sv * 0.125f;
}

__global__ void pool2_kernel() {
    int idx = blockIdx.x * blockDim.x + threadIdx.x;
    if (idx >= HH * 128 * DD) return;
    int dd = idx & (DD - 1);
    int c  = (idx / DD) & 127;
    int h  = idx / (DD * 128);
    const float* ks = g_k1 + ((size_t)h * 1024 + (size_t)c * 8) * DD + dd;
    const float* vs = g_v1 + ((size_t)h * 1024 + (size_t)c * 8) * DD + dd;
    float sk = 0.f, sv = 0.f;
#pragma unroll
    for (int r = 0; r < 8; r++) { sk += ks[r * DD]; sv += vs[r * DD]; }
    g_k2[idx] = sk * 0.125f;
    g_v2[idx] = sv * 0.125f;
}

__global__ void pool3_kernel() {
    int idx = blockIdx.x * blockDim.x + threadIdx.x;
    if (idx >= HH * 16 * DD) return;
    int dd = idx & (DD - 1);
    int c  = (idx / DD) & 15;
    int h  = idx / (DD * 16);
    const float* ks = g_k2 + ((size_t)h * 128 + (size_t)c * 8) * DD + dd;
    const float* vs = g_v2 + ((size_t)h * 128 + (size_t)c * 8) * DD + dd;
    float sk = 0.f, sv = 0.f;
#pragma unroll
    for (int r = 0; r < 8; r++) { sk += ks[r * DD]; sv += vs[r * DD]; }
    g_k3[idx] = sk * 0.125f;
    g_v3[idx] = sv * 0.125f;
}

// ---------------- attention ----------------
// Quarter-split, 2 queries per lane:
//   lane = 4a + qd; qd in 0..3 owns float4 slots {qd, qd+4, qd+8, qd+12} of d.
//   lane handles queries qi0 = qs + warp*16 + a and qi1 = qi0 + 8.
//   Quad reads 4 consecutive float4s per step -> 64B conflict-free wavefront.
//   Dots reduced within quad via shfl_xor(1), shfl_xor(2).
// Tiles double-buffered via cp.async (one barrier per tile).

__device__ __forceinline__ void online_update(float& m, float& l, u64* o,
                                              float sc, const ulonglong2* vv) {
    if (sc <= m) {
        float p = __expf(sc - m);
        l += p;
        u64 p2 = pack2(p);
#pragma unroll
        for (int t = 0; t < 4; t++) {
            ffma2(o[2 * t], p2, vv[t].x);
            ffma2(o[2 * t + 1], p2, vv[t].y);
        }
    } else {
        float c0 = __expf(m - sc);
        m = sc;
        l = fmaf(l, c0, 1.f);
        u64 c2 = pack2(c0);
#pragma unroll
        for (int t = 0; t < 4; t++) {
            fmul_add2(o[2 * t], c2, vv[t].x);
            fmul_add2(o[2 * t + 1], c2, vv[t].y);
        }
    }
}

// Prefetch one TS x 64 tile of K and V into smem buffers (row-clamped).
__device__ __forceinline__ void prefetch_tile(
    float4* kb, float4* vb,
    const float* __restrict__ kg, const float* __restrict__ vg,
    int row0, int rmax, int tid)
{
#pragma unroll
    for (int it = 0; it < 2; it++) {
        int e = tid + it * 256;        // e in [0, 512)
        int row = e >> 4, f4 = e & 15;
        int r = row0 + row;
        r = r < 0 ? 0 : (r > rmax ? rmax : r);
        cp16(kb + e, reinterpret_cast<const float4*>(kg + (size_t)r * DD) + f4);
        cp16(vb + e, reinterpret_cast<const float4*>(vg + (size_t)r * DD) + f4);
    }
    cp_commit();
}

__global__ void __launch_bounds__(256, 2) attn_kernel(
    const float* __restrict__ q, const float* __restrict__ k,
    const float* __restrict__ v, const float* __restrict__ gammas,
    float* __restrict__ out)
{
    __shared__ float4 kbuf[2][TS * 16];
    __shared__ float4 vbuf[2][TS * 16];

    int h = blockIdx.y;
    int qtile = (int)(gridDim.x - 1u - blockIdx.x);   // heavy tiles first
    int qs = qtile * 128;
    int tid = threadIdx.x;
    int warp = tid >> 5, lane = tid & 31;
    int qd = lane & 3;                 // quarter of d
    int a  = lane >> 2;                // 0..7
    int qi0 = qs + warp * 16 + a;
    int qi1 = qi0 + 8;
    int qi_wmin = qs + warp * 16;
    int qi_wmax = qi_wmin + 15;

    // q fragments: 4 float4s per query at slots qd + 4t
    ulonglong2 qp0[4], qp1[4];
    {
        const ulonglong2* qg0 = reinterpret_cast<const ulonglong2*>(
            q + ((size_t)h * NN + qi0) * DD);
        const ulonglong2* qg1 = reinterpret_cast<const ulonglong2*>(
            q + ((size_t)h * NN + qi1) * DD);
#pragma unroll
        for (int t = 0; t < 4; t++) { qp0[t] = qg0[qd + 4 * t]; qp1[t] = qg1[qd + 4 * t]; }
    }

    float m0 = NEGINF, l0 = 0.f, m1 = NEGINF, l1 = 0.f;
    u64 o0[8], o1[8];
#pragma unroll
    for (int t = 0; t < 8; t++) { o0[t] = 0ull; o1[t] = 0ull; }

    float gm0 = __ldg(&gammas[0]), gm1 = __ldg(&gammas[1]);
    float gm2 = __ldg(&gammas[2]), gm3 = __ldg(&gammas[3]);
    const float scale = 0.125f;

    // ================= Level 0: sliding window, nearest-first =================
    {
        const float* kg = k + (size_t)h * NN * DD;
        const float* vg = v + (size_t)h * NN * DD;
        const int nt = 256 / TS;                 // keys [qs-128, qs+128)
        prefetch_tile(kbuf[0], vbuf[0], kg, vg, qs + 128 - TS, NN - 1, tid);
#pragma unroll 1
        for (int it = 0; it < nt; it++) {
            cp_wait_all();
            __syncthreads();
            if (it + 1 < nt)
                prefetch_tile(kbuf[(it + 1) & 1], vbuf[(it + 1) & 1], kg, vg,
                              qs + 128 - (it + 2) * TS, NN - 1, tid);
            int tb = qs + 128 - (it + 1) * TS;
            const float4* kb = kbuf[it & 1];
            const float4* vb = vbuf[it & 1];
#pragma unroll 1
            for (int r = TS - 1; r >= 0; r--) {
                int j = tb + r;
                if (j > qi_wmax || j < qi_wmin - (WW - 1)) continue;  // warp-uniform
                const float4* kr = kb + (r * 16 + qd);
                u64 a00 = 0ull, a01 = 0ull, a10 = 0ull, a11 = 0ull;
#pragma unroll
                for (int t = 0; t < 4; t++) {
                    ulonglong2 kk = *reinterpret_cast<const ulonglong2*>(kr + 4 * t);
                    ffma2(a00, qp0[t].x, kk.x);
                    ffma2(a01, qp0[t].y, kk.y);
                    ffma2(a10, qp1[t].x, kk.x);
                    ffma2(a11, qp1[t].y, kk.y);
                }
                float2 f0 = unpack2(a00), f1 = unpack2(a01);
                float2 f2 = unpack2(a10), f3 = unpack2(a11);
                float s0 = (f0.x + f0.y) + (f1.x + f1.y);
                float s1 = (f2.x + f2.y) + (f3.x + f3.y);
                s0 += __shfl_xor_sync(0xffffffffu, s0, 1);
                s0 += __shfl_xor_sync(0xffffffffu, s0, 2);
                s1 += __shfl_xor_sync(0xffffffffu, s1, 1);
                s1 += __shfl_xor_sync(0xffffffffu, s1, 2);
                int d0 = qi0 - j, d1 = d0 + 8;
                float sc0 = fmaf(s0, scale, -gm0 * (float)d0);
                float sc1 = fmaf(s1, scale, -gm0 * (float)d1);
                bool vis0 = (j >= 0) & (d0 >= 0) & (d0 < WW);
                bool vis1 = (j >= 0) & (d1 >= 0) & (d1 < WW);
                if (vis0 | vis1) {
                    const float4* vr = vb + (r * 16 + qd);
                    ulonglong2 vv[4];
#pragma unroll
                    for (int t = 0; t < 4; t++)
                        vv[t] = *reinterpret_cast<const ulonglong2*>(vr + 4 * t);
                    if (vis0) online_update(m0, l0, o0, sc0, vv);
                    if (vis1) online_update(m1, l1, o1, sc1, vv);
                }
            }
        }
    }

    // ================= Levels 1..3: pooled chunks, nearest-first =================
#pragma unroll 1
    for (int lvl = 1; lvl <= 3; lvl++) {
        const float* kl; const float* vl; int C, S; float g;
        if (lvl == 1)      { kl = g_k1 + (size_t)h * 1024 * DD; vl = g_v1 + (size_t)h * 1024 * DD; C = 1024; S = 8;   g = gm1; }
        else if (lvl == 2) { kl = g_k2 + (size_t)h * 128  * DD; vl = g_v2 + (size_t)h * 128  * DD; C = 128;  S = 64;  g = gm2; }
        else               { kl = g_k3 + (size_t)h * 16   * DD; vl = g_v3 + (size_t)h * 16   * DD; C = 16;   S = 512; g = gm3; }
        int cmax = qs / S - 1;          // max visible chunk for block's top query
        if (cmax < 0) continue;
        int nt = cmax / TS + 1;
        __syncthreads();                 // protect buffers from previous level
        prefetch_tile(kbuf[0], vbuf[0], kl, vl, (nt - 1) * TS, C - 1, tid);
#pragma unroll 1
        for (int it = 0; it < nt; it++) {
            cp_wait_all();
            __syncthreads();
            if (it + 1 < nt)
                prefetch_tile(kbuf[(it + 1) & 1], vbuf[(it + 1) & 1], kl, vl,
                              (nt - 2 - it) * TS, C - 1, tid);
            int cb = (nt - 1 - it) * TS;
            const float4* kb = kbuf[it & 1];
            const float4* vb = vbuf[it & 1];
#pragma unroll 1
            for (int r = TS - 1; r >= 0; r--) {
                int c = cb + r;
                int jl = (c + 1) * S - 1;
                if (qi_wmax - jl < WW) continue;   // warp-uniform: invisible row
                const float4* kr = kb + (r * 16 + qd);
                u64 a00 = 0ull, a01 = 0ull, a10 = 0ull, a11 = 0ull;
#pragma unroll
                for (int t = 0; t < 4; t++) {
                    ulonglong2 kk = *reinterpret_cast<const ulonglong2*>(kr + 4 * t);
                    ffma2(a00, qp0[t].x, kk.x);
                    ffma2(a01, qp0[t].y, kk.y);
                    ffma2(a10, qp1[t].x, kk.x);
                    ffma2(a11, qp1[t].y, kk.y);
                }
                float2 f0 = unpack2(a00), f1 = unpack2(a01);
                float2 f2 = unpack2(a10), f3 = unpack2(a11);
                float s0 = (f0.x + f0.y) + (f1.x + f1.y);
                float s1 = (f2.x + f2.y) + (f3.x + f3.y);
                s0 += __shfl_xor_sync(0xffffffffu, s0, 1);
                s0 += __shfl_xor_sync(0xffffffffu, s0, 2);
                s1 += __shfl_xor_sync(0xffffffffu, s1, 1);
                s1 += __shfl_xor_sync(0xffffffffu, s1, 2);
                int d0 = qi0 - jl, d1 = d0 + 8;
                float sc0 = fmaf(s0, scale, -g * (float)d0);
                float sc1 = fmaf(s1, scale, -g * (float)d1);
                bool vis0 = d0 >= WW;
                bool vis1 = d1 >= WW;
                if (vis0 | vis1) {
                    const float4* vr = vb + (r * 16 + qd);
                    ulonglong2 vv[4];
#pragma unroll
                    for (int t = 0; t < 4; t++)
                        vv[t] = *reinterpret_cast<const ulonglong2*>(vr + 4 * t);
                    if (vis0) online_update(m0, l0, o0, sc0, vv);
                    if (vis1) online_update(m1, l1, o1, sc1, vv);
                }
            }
        }
    }

    // ================= write out = o / clip(l, 1e-8) =================
    {
        float inv0 = 1.0f / fmaxf(l0, 1e-8f);
        float inv1 = 1.0f / fmaxf(l1, 1e-8f);
        u64 i20 = pack2(inv0), i21 = pack2(inv1);
        ulonglong2* og0 = reinterpret_cast<ulonglong2*>(out + ((size_t)h * NN + qi0) * DD);
        ulonglong2* og1 = reinterpret_cast<ulonglong2*>(out + ((size_t)h * NN + qi1) * DD);
#pragma unroll
        for (int t = 0; t < 4; t++) {
            ulonglong2 w0, w1;
            w0.x = mul2(o0[2 * t], i20); w0.y = mul2(o0[2 * t + 1], i20);
            w1.x = mul2(o1[2 * t], i21); w1.y = mul2(o1[2 * t + 1], i21);
            og0[qd + 4 * t] = w0;
            og1[qd + 4 * t] = w1;
        }
    }
}

// ---------------- launch ----------------
extern "C" void kernel_launch(void* const* d_in, const int* in_sizes, int n_in,
                              void* d_out, int out_size) {
    const float* q      = (const float*)d_in[0];
    const float* k      = (const float*)d_in[1];
    const float* v      = (const float*)d_in[2];
    const float* gammas = (const float*)d_in[3];
    float* out = (float*)d_out;

    pool1_kernel<<<(HH * 1024 * DD + 255) / 256, 256>>>(k, v);
    pool2_kernel<<<(HH * 128 * DD + 255) / 256, 256>>>();
    pool3_kernel<<<(HH * 16 * DD + 255) / 256, 256>>>();

    dim3 grid(NN / 128, HH);
    attn_kernel<<<grid, 256>>>(q, k, v, gammas, out);
}

// round 9
// speedup vs baseline: 1.8776x; 1.8776x over previous
#include <cuda_runtime.h>

#define HH 16
#define NN 8192
#define DD 64
#define WW 128
#define NEGV (-1e30f)
#define KSTR 68
#define VSTR 72

// Pooled K/V scratch (allocation-free: __device__ globals)
__device__ float g_k1[HH * 1024 * DD];
__device__ float g_v1[HH * 1024 * DD];
__device__ float g_k2[HH * 128 * DD];
__device__ float g_v2[HH * 128 * DD];
__device__ float g_k3[HH * 16 * DD];
__device__ float g_v3[HH * 16 * DD];

// ---------------- mma + cvt + cp.async helpers ----------------
__device__ __forceinline__ void mma_tf32(
    float& d0, float& d1, float& d2, float& d3,
    unsigned a0, unsigned a1, unsigned a2, unsigned a3,
    unsigned b0, unsigned b1)
{
    asm volatile(
        "mma.sync.aligned.m16n8k8.row.col.f32.tf32.tf32.f32 "
        "{%0,%1,%2,%3}, {%4,%5,%6,%7}, {%8,%9}, {%0,%1,%2,%3};\n"
        : "+f"(d0), "+f"(d1), "+f"(d2), "+f"(d3)
        : "r"(a0), "r"(a1), "r"(a2), "r"(a3), "r"(b0), "r"(b1));
}

// round-to-nearest tf32 (result is f32-container with low mantissa bits zero)
__device__ __forceinline__ unsigned t32(float x) {
    unsigned r; asm("cvt.rna.tf32.f32 %0, %1;" : "=r"(r) : "f"(x)); return r;
}

__device__ __forceinline__ void cp16(const void* smem_dst, const void* gsrc) {
    unsigned sa = (unsigned)__cvta_generic_to_shared(smem_dst);
    asm volatile("cp.async.cg.shared.global [%0], [%1], 16;" :: "r"(sa), "l"(gsrc));
}
__device__ __forceinline__ void cp_commit() {
    asm volatile("cp.async.commit_group;" ::: "memory");
}
__device__ __forceinline__ void cp_wait_all() {
    asm volatile("cp.async.wait_group 0;" ::: "memory");
}

// ---------------- pooling kernels (exact fp32, unchanged) ----------------
__global__ void pool1_kernel(const float* __restrict__ k, const float* __restrict__ v) {
    int idx = blockIdx.x * blockDim.x + threadIdx.x;
    if (idx >= HH * 1024 * DD) return;
    int dd = idx & (DD - 1);
    int c  = (idx / DD) & 1023;
    int h  = idx / (DD * 1024);
    const float* ks = k + ((size_t)h * NN + (size_t)c * 8) * DD + dd;
    const float* vs = v + ((size_t)h * NN + (size_t)c * 8) * DD + dd;
    float sk = 0.f, sv = 0.f;
#pragma unroll
    for (int r = 0; r < 8; r++) { sk += ks[r * DD]; sv += vs[r * DD]; }
    g_k1[idx] = sk * 0.125f;
    g_v1[idx] = sv * 0.125f;
}

__global__ void pool2_kernel() {
    int idx = blockIdx.x * blockDim.x + threadIdx.x;
    if (idx >= HH * 128 * DD) return;
    int dd = idx & (DD - 1);
    int c  = (idx / DD) & 127;
    int h  = idx / (DD * 128);
    const float* ks = g_k1 + ((size_t)h * 1024 + (size_t)c * 8) * DD + dd;
    const float* vs = g_v1 + ((size_t)h * 1024 + (size_t)c * 8) * DD + dd;
    float sk = 0.f, sv = 0.f;
#pragma unroll
    for (int r = 0; r < 8; r++) { sk += ks[r * DD]; sv += vs[r * DD]; }
    g_k2[idx] = sk * 0.125f;
    g_v2[idx] = sv * 0.125f;
}

__global__ void pool3_kernel() {
    int idx = blockIdx.x * blockDim.x + threadIdx.x;
    if (idx >= HH * 16 * DD) return;
    int dd = idx & (DD - 1);
    int c  = (idx / DD) & 15;
    int h  = idx / (DD * 16);
    const float* ks = g_k2 + ((size_t)h * 128 + (size_t)c * 8) * DD + dd;
    const float* vs = g_v2 + ((size_t)h * 128 + (size_t)c * 8) * DD + dd;
    float sk = 0.f, sv = 0.f;
#pragma unroll
    for (int r = 0; r < 8; r++) { sk += ks[r * DD]; sv += vs[r * DD]; }
    g_k3[idx] = sk * 0.125f;
    g_v3[idx] = sv * 0.125f;
}

// Prefetch one 32-row x 64-col tile of K and V (row-clamped) into padded smem.
__device__ __forceinline__ void prefetch_tile(
    float* ks, float* vs,
    const float* __restrict__ kg, const float* __restrict__ vg,
    int row0, int rmax, int tid)
{
#pragma unroll
    for (int it = 0; it < 2; it++) {
        int e = tid + it * 256;          // e in [0, 512)
        int row = e >> 4, f4 = e & 15;
        int r = row0 + row;
        r = r < 0 ? 0 : (r > rmax ? rmax : r);
        cp16(ks + row * KSTR + f4 * 4, kg + (size_t)r * DD + f4 * 4);
        cp16(vs + row * VSTR + f4 * 4, vg + (size_t)r * DD + f4 * 4);
    }
    cp_commit();
}

// ---------------- FA2-style tensor-core attention, 3xTF32 ----------------
// CTA = 128 queries x 1 head; 8 warps, warp owns 16 rows.
// Each operand split x = hi + lo (hi = rna-tf32); accumulate
// hi*hi + hi*lo + lo*hi -> near-fp32 accuracy at 3x MMA cost.

__global__ void __launch_bounds__(256, 2) attn_kernel(
    const float* __restrict__ q, const float* __restrict__ k,
    const float* __restrict__ v, const float* __restrict__ gammas,
    float* __restrict__ out)
{
    __shared__ float ksm[2][32 * KSTR];
    __shared__ float vsm[2][32 * VSTR];

    int h = blockIdx.y;
    int qtile = (int)(gridDim.x - 1u - blockIdx.x);   // heavy tiles first
    int qs = qtile * 128;
    int tid = threadIdx.x;
    int warp = tid >> 5, lane = tid & 31;
    int r0 = qs + warp * 16;
    int g = lane >> 2, c = lane & 3;
    int cc = 2 * c;
    int i0 = r0 + g, i1 = i0 + 8;
    bool sel = (lane & 1);
    unsigned src1 = (unsigned)((lane & ~3) | (c >> 1));
    unsigned src2 = src1 + 2;

    // Q A-fragments kept in fp32; hi/lo rebuilt per k-step.
    float qa[8][4];
    {
        const float* q0p = q + ((size_t)h * NN + i0) * DD;
        const float* q1p = q + ((size_t)h * NN + i1) * DD;
#pragma unroll
        for (int ks_ = 0; ks_ < 8; ks_++) {
            qa[ks_][0] = q0p[8 * ks_ + c];
            qa[ks_][1] = q1p[8 * ks_ + c];
            qa[ks_][2] = q0p[8 * ks_ + c + 4];
            qa[ks_][3] = q1p[8 * ks_ + c + 4];
        }
    }

    float m0 = NEGV, m1 = NEGV, l0 = 0.f, l1 = 0.f;
    float O[8][4];
#pragma unroll
    for (int n = 0; n < 8; n++) { O[n][0] = O[n][1] = O[n][2] = O[n][3] = 0.f; }

    float gm0 = __ldg(&gammas[0]), gm1 = __ldg(&gammas[1]);
    float gm2 = __ldg(&gammas[2]), gm3 = __ldg(&gammas[3]);
    const float scale = 0.125f;

    auto do_tile = [&](const float* ks_, const float* vs_, bool L0,
                       int base, int S, float gamma) {
        float s[4][4];
#pragma unroll
        for (int n = 0; n < 4; n++) { s[n][0] = s[n][1] = s[n][2] = s[n][3] = 0.f; }

        // ---- QK^T: S[16 x 32], 3xTF32 ----
        const float* kb = ks_ + g * KSTR + c;
#pragma unroll
        for (int ks2 = 0; ks2 < 8; ks2++) {
            unsigned ah[4], al[4];
#pragma unroll
            for (int t = 0; t < 4; t++) {
                ah[t] = t32(qa[ks2][t]);
                al[t] = __float_as_uint(qa[ks2][t] - __uint_as_float(ah[t]));
            }
#pragma unroll
            for (int n = 0; n < 4; n++) {
                float b0f = kb[n * 8 * KSTR + ks2 * 8];
                float b1f = kb[n * 8 * KSTR + ks2 * 8 + 4];
                unsigned bh0 = t32(b0f), bh1 = t32(b1f);
                unsigned bl0 = __float_as_uint(b0f - __uint_as_float(bh0));
                unsigned bl1 = __float_as_uint(b1f - __uint_as_float(bh1));
                mma_tf32(s[n][0], s[n][1], s[n][2], s[n][3],
                         ah[0], ah[1], ah[2], ah[3], bh0, bh1);
                mma_tf32(s[n][0], s[n][1], s[n][2], s[n][3],
                         ah[0], ah[1], ah[2], ah[3], bl0, bl1);
                mma_tf32(s[n][0], s[n][1], s[n][2], s[n][3],
                         al[0], al[1], al[2], al[3], bh0, bh1);
            }
        }

        // ---- mask + ALiBi bias ----
#pragma unroll
        for (int n = 0; n < 4; n++) {
            int colA = 8 * n + cc;
            if (L0) {
                int jA = base + colA, jB = jA + 1;
                int dA0 = i0 - jA, dB0 = dA0 - 1;
                int dA1 = dA0 + 8, dB1 = dA1 - 1;
                s[n][0] = (jA >= 0 && (unsigned)dA0 < WW) ? fmaf(s[n][0], scale, -gamma * (float)dA0) : NEGV;
                s[n][1] = (jB >= 0 && (unsigned)dB0 < WW) ? fmaf(s[n][1], scale, -gamma * (float)dB0) : NEGV;
                s[n][2] = (jA >= 0 && (unsigned)dA1 < WW) ? fmaf(s[n][2], scale, -gamma * (float)dA1) : NEGV;
                s[n][3] = (jB >= 0 && (unsigned)dB1 < WW) ? fmaf(s[n][3], scale, -gamma * (float)dB1) : NEGV;
            } else {
                int jlA = (base + colA + 1) * S - 1;
                int jlB = jlA + S;
                int dA0 = i0 - jlA, dB0 = i0 - jlB;
                int dA1 = dA0 + 8, dB1 = dB0 + 8;
                s[n][0] = (dA0 >= WW) ? fmaf(s[n][0], scale, -gamma * (float)dA0) : NEGV;
                s[n][1] = (dB0 >= WW) ? fmaf(s[n][1], scale, -gamma * (float)dB0) : NEGV;
                s[n][2] = (dA1 >= WW) ? fmaf(s[n][2], scale, -gamma * (float)dA1) : NEGV;
                s[n][3] = (dB1 >= WW) ? fmaf(s[n][3], scale, -gamma * (float)dB1) : NEGV;
            }
        }

        // ---- online softmax ----
        float ml0 = s[0][0], ml1 = s[0][2];
#pragma unroll
        for (int n = 0; n < 4; n++) {
            ml0 = fmaxf(ml0, fmaxf(s[n][0], s[n][1]));
            ml1 = fmaxf(ml1, fmaxf(s[n][2], s[n][3]));
        }
        ml0 = fmaxf(ml0, __shfl_xor_sync(0xffffffffu, ml0, 1));
        ml0 = fmaxf(ml0, __shfl_xor_sync(0xffffffffu, ml0, 2));
        ml1 = fmaxf(ml1, __shfl_xor_sync(0xffffffffu, ml1, 1));
        ml1 = fmaxf(ml1, __shfl_xor_sync(0xffffffffu, ml1, 2));
        float nm0 = fmaxf(m0, ml0), nm1 = fmaxf(m1, ml1);
        float e0 = __expf(m0 - nm0), e1 = __expf(m1 - nm1);
        m0 = nm0; m1 = nm1;
        float sum0 = 0.f, sum1 = 0.f;
#pragma unroll
        for (int n = 0; n < 4; n++) {
            s[n][0] = __expf(s[n][0] - nm0); sum0 += s[n][0];
            s[n][1] = __expf(s[n][1] - nm0); sum0 += s[n][1];
            s[n][2] = __expf(s[n][2] - nm1); sum1 += s[n][2];
            s[n][3] = __expf(s[n][3] - nm1); sum1 += s[n][3];
        }
        l0 = fmaf(l0, e0, sum0);
        l1 = fmaf(l1, e1, sum1);
        if (!__all_sync(0xffffffffu, (e0 == 1.f) && (e1 == 1.f))) {
#pragma unroll
            for (int n = 0; n < 8; n++) {
                O[n][0] *= e0; O[n][1] *= e0; O[n][2] *= e1; O[n][3] *= e1;
            }
        }

        // ---- O += P V, 3xTF32 (repack C-frag -> A-frag per 8-key step) ----
#pragma unroll
        for (int kt = 0; kt < 4; kt++) {
            float t0 = __shfl_sync(0xffffffffu, s[kt][0], src1);
            float t1 = __shfl_sync(0xffffffffu, s[kt][1], src1);
            float t2 = __shfl_sync(0xffffffffu, s[kt][2], src1);
            float t3 = __shfl_sync(0xffffffffu, s[kt][3], src1);
            float u0 = __shfl_sync(0xffffffffu, s[kt][0], src2);
            float u1 = __shfl_sync(0xffffffffu, s[kt][1], src2);
            float u2 = __shfl_sync(0xffffffffu, s[kt][2], src2);
            float u3 = __shfl_sync(0xffffffffu, s[kt][3], src2);
            float Af[4];
            Af[0] = sel ? t1 : t0;
            Af[1] = sel ? t3 : t2;
            Af[2] = sel ? u1 : u0;
            Af[3] = sel ? u3 : u2;
            unsigned Ah[4], Al[4];
#pragma unroll
            for (int t = 0; t < 4; t++) {
                Ah[t] = t32(Af[t]);
                Al[t] = __float_as_uint(Af[t] - __uint_as_float(Ah[t]));
            }
            const float* vb = vs_ + (8 * kt + c) * VSTR + g;
#pragma unroll
            for (int n = 0; n < 8; n++) {
                float b0f = vb[8 * n];
                float b1f = vb[8 * n + 4 * VSTR];
                unsigned bh0 = t32(b0f), bh1 = t32(b1f);
                unsigned bl0 = __float_as_uint(b0f - __uint_as_float(bh0));
                unsigned bl1 = __float_as_uint(b1f - __uint_as_float(bh1));
                mma_tf32(O[n][0], O[n][1], O[n][2], O[n][3],
                         Ah[0], Ah[1], Ah[2], Ah[3], bh0, bh1);
                mma_tf32(O[n][0], O[n][1], O[n][2], O[n][3],
                         Ah[0], Ah[1], Ah[2], Ah[3], bl0, bl1);
                mma_tf32(O[n][0], O[n][1], O[n][2], O[n][3],
                         Al[0], Al[1], Al[2], Al[3], bh0, bh1);
            }
        }
    };

    // ================= Level 0: sliding window, nearest-first =================
    {
        const float* kg = k + (size_t)h * NN * DD;
        const float* vg = v + (size_t)h * NN * DD;
        prefetch_tile(ksm[0], vsm[0], kg, vg, qs + 128 - 32, NN - 1, tid);
#pragma unroll 1
        for (int it = 0; it < 8; it++) {
            cp_wait_all();
            __syncthreads();
            if (it + 1 < 8)
                prefetch_tile(ksm[(it + 1) & 1], vsm[(it + 1) & 1], kg, vg,
                              qs + 128 - (it + 2) * 32, NN - 1, tid);
            int tb = qs + 128 - (it + 1) * 32;
            bool skip = (tb > r0 + 15) || (tb + 31 < r0 - (WW - 1));
            if (!skip) do_tile(ksm[it & 1], vsm[it & 1], true, tb, 1, gm0);
        }
    }

    // ================= Levels 1..3: pooled chunks, nearest-first =================
#pragma unroll 1
    for (int lvl = 1; lvl <= 3; lvl++) {
        const float* kl; const float* vl; int C, S; float gamma;
        if (lvl == 1)      { kl = g_k1 + (size_t)h * 1024 * DD; vl = g_v1 + (size_t)h * 1024 * DD; C = 1024; S = 8;   gamma = gm1; }
        else if (lvl == 2) { kl = g_k2 + (size_t)h * 128  * DD; vl = g_v2 + (size_t)h * 128  * DD; C = 128;  S = 64;  gamma = gm2; }
        else               { kl = g_k3 + (size_t)h * 16   * DD; vl = g_v3 + (size_t)h * 16   * DD; C = 16;   S = 512; gamma = gm3; }
        int cmax = qs / S - 1;                 // block-level max visible chunk
        if (cmax < 0) continue;
        int nt = cmax / 32 + 1;
        // warp-level max visible chunk for row r0+15
        int cwmax = (r0 >= 112 + S) ? ((r0 - 112) / S - 1 + 1) - 1 : -1;
        __syncthreads();                        // previous buffers done
        prefetch_tile(ksm[0], vsm[0], kl, vl, (nt - 1) * 32, C - 1, tid);
#pragma unroll 1
        for (int it = 0; it < nt; it++) {
            cp_wait_all();
            __syncthreads();
            if (it + 1 < nt)
                prefetch_tile(ksm[(it + 1) & 1], vsm[(it + 1) & 1], kl, vl,
                              (nt - 2 - it) * 32, C - 1, tid);
            int cb = (nt - 1 - it) * 32;
            if (cb <= cwmax) do_tile(ksm[it & 1], vsm[it & 1], false, cb, S, gamma);
        }
    }

    // ================= epilogue: out = O / clip(l, 1e-8) =================
    l0 += __shfl_xor_sync(0xffffffffu, l0, 1);
    l0 += __shfl_xor_sync(0xffffffffu, l0, 2);
    l1 += __shfl_xor_sync(0xffffffffu, l1, 1);
    l1 += __shfl_xor_sync(0xffffffffu, l1, 2);
    float inv0 = 1.0f / fmaxf(l0, 1e-8f);
    float inv1 = 1.0f / fmaxf(l1, 1e-8f);
    float* o0p = out + ((size_t)h * NN + i0) * DD;
    float* o1p = out + ((size_t)h * NN + i1) * DD;
#pragma unroll
    for (int n = 0; n < 8; n++) {
        float2 w0 = make_float2(O[n][0] * inv0, O[n][1] * inv0);
        float2 w1 = make_float2(O[n][2] * inv1, O[n][3] * inv1);
        *reinterpret_cast<float2*>(o0p + 8 * n + cc) = w0;
        *reinterpret_cast<float2*>(o1p + 8 * n + cc) = w1;
    }
}

// ---------------- launch ----------------
extern "C" void kernel_launch(void* const* d_in, const int* in_sizes, int n_in,
                              void* d_out, int out_size) {
    const float* q      = (const float*)d_in[0];
    const float* k      = (const float*)d_in[1];
    const float* v      = (const float*)d_in[2];
    const float* gammas = (const float*)d_in[3];
    float* out = (float*)d_out;

    pool1_kernel<<<(HH * 1024 * DD + 255) / 256, 256>>>(k, v);
    pool2_kernel<<<(HH * 128 * DD + 255) / 256, 256>>>();
    pool3_kernel<<<(HH * 16 * DD + 255) / 256, 256>>>();

    dim3 grid(NN / 128, HH);
    attn_kernel<<<grid, 256>>>(q, k, v, gammas, out);
}

// round 11
// speedup vs baseline: 3.3285x; 1.7728x over previous
#include <cuda_runtime.h>
#include <cuda_bf16.h>

#define HH 16
#define NN 8192
#define DD 64
#define WW 128
#define NEGV (-1e30f)
#define RSK 36   // words per K-plane smem row (32 data + 4 pad)
#define RSV 20   // words per V-plane smem row (16 data + 4 pad)

typedef unsigned short u16;
typedef unsigned int u32;

// ---------------- fp32 pooled intermediates ----------------
__device__ float g_k1[HH * 1024 * DD];
__device__ float g_v1[HH * 1024 * DD];
__device__ float g_k2[HH * 128 * DD];
__device__ float g_v2[HH * 128 * DD];
__device__ float g_k3[HH * 16 * DD];
__device__ float g_v3[HH * 16 * DD];

// ---------------- bf16 hi/lo split planes ----------------
// K planes: [h][key][d] (d-major). V planes: [h][d][key] (transposed).
__device__ u16 g_kh0[HH * NN * DD],   g_kl0[HH * NN * DD];
__device__ u16 g_vh0[HH * DD * NN],   g_vl0[HH * DD * NN];
__device__ u16 g_kh1[HH * 1024 * DD], g_kl1[HH * 1024 * DD];
__device__ u16 g_vh1[HH * DD * 1024], g_vl1[HH * DD * 1024];
__device__ u16 g_kh2[HH * 128 * DD],  g_kl2[HH * 128 * DD];
__device__ u16 g_vh2[HH * DD * 128],  g_vl2[HH * DD * 128];
__device__ u16 g_kh3[HH * 16 * DD],   g_kl3[HH * 16 * DD];
__device__ u16 g_vh3[HH * DD * 16],   g_vl3[HH * DD * 16];

// ---------------- helpers ----------------
__device__ __forceinline__ void mma_bf16(
    float& d0, float& d1, float& d2, float& d3,
    u32 a0, u32 a1, u32 a2, u32 a3, u32 b0, u32 b1)
{
    asm volatile(
        "mma.sync.aligned.m16n8k16.row.col.f32.bf16.bf16.f32 "
        "{%0,%1,%2,%3}, {%4,%5,%6,%7}, {%8,%9}, {%0,%1,%2,%3};\n"
        : "+f"(d0), "+f"(d1), "+f"(d2), "+f"(d3)
        : "r"(a0), "r"(a1), "r"(a2), "r"(a3), "r"(b0), "r"(b1));
}

// pack two f32 -> bf16x2 (e0 in low 16 bits)
__device__ __forceinline__ u32 packbf(float e0, float e1) {
    u32 r; asm("cvt.rn.bf16x2.f32 %0, %1, %2;" : "=r"(r) : "f"(e1), "f"(e0));
    return r;
}
// split pair into hi bf16x2 + lo bf16x2 (error-free residual)
__device__ __forceinline__ void split2(float x0, float x1, u32& hi, u32& lo) {
    hi = packbf(x0, x1);
    float h0 = __uint_as_float(hi << 16);
    float h1 = __uint_as_float(hi & 0xffff0000u);
    lo = packbf(x0 - h0, x1 - h1);
}

__device__ __forceinline__ void cp16(const void* smem_dst, const void* gsrc) {
    unsigned sa = (unsigned)__cvta_generic_to_shared(smem_dst);
    asm volatile("cp.async.cg.shared.global [%0], [%1], 16;" :: "r"(sa), "l"(gsrc));
}
__device__ __forceinline__ void cp_commit() {
    asm volatile("cp.async.commit_group;" ::: "memory");
}
__device__ __forceinline__ void cp_wait_all() {
    asm volatile("cp.async.wait_group 0;" ::: "memory");
}

// ---------------- pooling kernels (exact fp32) ----------------
__global__ void pool1_kernel(const float* __restrict__ k, const float* __restrict__ v) {
    int idx = blockIdx.x * blockDim.x + threadIdx.x;
    if (idx >= HH * 1024 * DD) return;
    int dd = idx & (DD - 1);
    int c  = (idx / DD) & 1023;
    int h  = idx / (DD * 1024);
    const float* ks = k + ((size_t)h * NN + (size_t)c * 8) * DD + dd;
    const float* vs = v + ((size_t)h * NN + (size_t)c * 8) * DD + dd;
    float sk = 0.f, sv = 0.f;
#pragma unroll
    for (int r = 0; r < 8; r++) { sk += ks[r * DD]; sv += vs[r * DD]; }
    g_k1[idx] = sk * 0.125f;
    g_v1[idx] = sv * 0.125f;
}

__global__ void pool2_kernel() {
    int idx = blockIdx.x * blockDim.x + threadIdx.x;
    if (idx >= HH * 128 * DD) return;
    int dd = idx & (DD - 1);
    int c  = (idx / DD) & 127;
    int h  = idx / (DD * 128);
    const float* ks = g_k1 + ((size_t)h * 1024 + (size_t)c * 8) * DD + dd;
    const float* vs = g_v1 + ((size_t)h * 1024 + (size_t)c * 8) * DD + dd;
    float sk = 0.f, sv = 0.f;
#pragma unroll
    for (int r = 0; r < 8; r++) { sk += ks[r * DD]; sv += vs[r * DD]; }
    g_k2[idx] = sk * 0.125f;
    g_v2[idx] = sv * 0.125f;
}

__global__ void pool3_kernel() {
    int idx = blockIdx.x * blockDim.x + threadIdx.x;
    if (idx >= HH * 16 * DD) return;
    int dd = idx & (DD - 1);
    int c  = (idx / DD) & 15;
    int h  = idx / (DD * 16);
    const float* ks = g_k2 + ((size_t)h * 128 + (size_t)c * 8) * DD + dd;
    const float* vs = g_v2 + ((size_t)h * 128 + (size_t)c * 8) * DD + dd;
    float sk = 0.f, sv = 0.f;
#pragma unroll
    for (int r = 0; r < 8; r++) { sk += ks[r * DD]; sv += vs[r * DD]; }
    g_k3[idx] = sk * 0.125f;
    g_v3[idx] = sv * 0.125f;
}

// ---------------- split + transpose kernel ----------------
// Per block: 32-key x 64-d tile of one head. K split written in place
// (d-major); V split transposed to [d][key] via smem staging.
__global__ void split_tr_kernel(const float* __restrict__ ksrc,
                                const float* __restrict__ vsrc, int C,
                                u16* __restrict__ khi, u16* __restrict__ klo,
                                u16* __restrict__ vhi, u16* __restrict__ vlo)
{
    __shared__ u16 sh[DD][34], sl[DD][34];
    int h = blockIdx.y, k0 = blockIdx.x * 32;
    int tid = threadIdx.x;
#pragma unroll 1
    for (int e = tid; e < 32 * DD; e += 256) {
        int key = k0 + (e >> 6), d = e & 63;
        if (key < C) {
            size_t off = ((size_t)h * C + key) * DD + d;
            float x = ksrc[off];
            __nv_bfloat16 xb = __float2bfloat16(x);
            u16 xh = *reinterpret_cast<u16*>(&xb);
            float xr = x - __bfloat162float(xb);
            __nv_bfloat16 xrb = __float2bfloat16(xr);
            khi[off] = xh;
            klo[off] = *reinterpret_cast<u16*>(&xrb);
            float y = vsrc[off];
            __nv_bfloat16 yb = __float2bfloat16(y);
            float yr = y - __bfloat162float(yb);
            __nv_bfloat16 yrb = __float2bfloat16(yr);
            sh[d][key - k0] = *reinterpret_cast<u16*>(&yb);
            sl[d][key - k0] = *reinterpret_cast<u16*>(&yrb);
        }
    }
    __syncthreads();
#pragma unroll 1
    for (int e = tid; e < 32 * DD; e += 256) {
        int d = e >> 5, kk = e & 31;
        if (k0 + kk < C) {
            size_t off = ((size_t)h * DD + d) * C + k0 + kk;
            vhi[off] = sh[d][kk];
            vlo[off] = sl[d][kk];
        }
    }
}

// ---------------- tile prefetch (all four planes) ----------------
__device__ __forceinline__ void prefetch_planes(
    u32* khs, u32* kls, u32* vhs, u32* vls,
    const u16* __restrict__ khg, const u16* __restrict__ klg,
    const u16* __restrict__ vhg, const u16* __restrict__ vlg,
    int C, int tb, int tid)
{
    {   // K planes: 32 rows x 128B
        int row = tid >> 3, ch = tid & 7;
        int r = tb + row;
        r = r < 0 ? 0 : (r > C - 1 ? C - 1 : r);
        size_t so = (size_t)r * DD + ch * 8;
        cp16(khs + row * RSK + ch * 4, khg + so);
        cp16(kls + row * RSK + ch * 4, klg + so);
    }
    {   // V planes (transposed): 64 d-rows x 64B
        int d = tid >> 2, ch = tid & 3;
        int k0 = tb + ch * 8;
        k0 = k0 < 0 ? 0 : (k0 > C - 8 ? C - 8 : k0);
        size_t so = (size_t)d * C + k0;
        cp16(vhs + d * RSV + ch * 4, vhg + so);
        cp16(vls + d * RSV + ch * 4, vlg + so);
    }
    cp_commit();
}

// ---------------- FA2 bf16-split attention ----------------
// CTA = 128 queries x 1 head; 8 warps x 16 rows. m16n8k16 bf16, 3-term split:
// Ah*Bh + Ah*Bl + Al*Bh. All K/V splits precomputed; Q split once in regs;
// P split per tile (no shuffle repack: k16 A-frag pairs == C-frag pairs).

__global__ void __launch_bounds__(256, 2) attn_kernel(
    const float* __restrict__ q, const float* __restrict__ gammas,
    float* __restrict__ out)
{
    __shared__ u32 skh[2][32 * RSK], skl[2][32 * RSK];
    __shared__ u32 svh[2][DD * RSV], svl[2][DD * RSV];

    int h = blockIdx.y;
    int qtile = (int)(gridDim.x - 1u - blockIdx.x);   // heavy tiles first
    int qs = qtile * 128;
    int tid = threadIdx.x;
    int warp = tid >> 5, lane = tid & 31;
    int r0 = qs + warp * 16;
    int g = lane >> 2, c = lane & 3;
    int cc = 2 * c;
    int i0 = r0 + g, i1 = i0 + 8;

    // Q split once: qh/ql[ks][0..3] (bf16x2 fragments for 4 k16-steps)
    u32 qh[4][4], ql[4][4];
    {
        const float* q0p = q + ((size_t)h * NN + i0) * DD;
        const float* q1p = q + ((size_t)h * NN + i1) * DD;
#pragma unroll
        for (int ks = 0; ks < 4; ks++) {
            split2(q0p[16 * ks + cc],     q0p[16 * ks + cc + 1], qh[ks][0], ql[ks][0]);
            split2(q1p[16 * ks + cc],     q1p[16 * ks + cc + 1], qh[ks][1], ql[ks][1]);
            split2(q0p[16 * ks + cc + 8], q0p[16 * ks + cc + 9], qh[ks][2], ql[ks][2]);
            split2(q1p[16 * ks + cc + 8], q1p[16 * ks + cc + 9], qh[ks][3], ql[ks][3]);
        }
    }

    float m0 = NEGV, m1 = NEGV, l0 = 0.f, l1 = 0.f;
    float O[8][4];
#pragma unroll
    for (int n = 0; n < 8; n++) { O[n][0] = O[n][1] = O[n][2] = O[n][3] = 0.f; }

    float gm0 = __ldg(&gammas[0]), gm1 = __ldg(&gammas[1]);
    float gm2 = __ldg(&gammas[2]), gm3 = __ldg(&gammas[3]);
    const float scale = 0.125f;

    auto do_tile = [&](const u32* kh, const u32* kl, const u32* vh, const u32* vl,
                       bool L0, int base, int S, float gamma) {
        float s[4][4];
#pragma unroll
        for (int n = 0; n < 4; n++) { s[n][0] = s[n][1] = s[n][2] = s[n][3] = 0.f; }

        // ---- QK^T: 4 n-steps x 4 k-steps x 3 MMA ----
#pragma unroll
        for (int nb = 0; nb < 4; nb++) {
            const u32* ph = kh + (nb * 8 + g) * RSK + c;
            const u32* pl = kl + (nb * 8 + g) * RSK + c;
#pragma unroll
            for (int ks = 0; ks < 4; ks++) {
                u32 bh0 = ph[8 * ks], bh1 = ph[8 * ks + 4];
                u32 bl0 = pl[8 * ks], bl1 = pl[8 * ks + 4];
                mma_bf16(s[nb][0], s[nb][1], s[nb][2], s[nb][3],
                         qh[ks][0], qh[ks][1], qh[ks][2], qh[ks][3], bh0, bh1);
                mma_bf16(s[nb][0], s[nb][1], s[nb][2], s[nb][3],
                         qh[ks][0], qh[ks][1], qh[ks][2], qh[ks][3], bl0, bl1);
                mma_bf16(s[nb][0], s[nb][1], s[nb][2], s[nb][3],
                         ql[ks][0], ql[ks][1], ql[ks][2], ql[ks][3], bh0, bh1);
            }
        }

        // ---- mask + ALiBi bias (C-frag: cols 8n+2c, 8n+2c+1; rows i0/i1) ----
#pragma unroll
        for (int n = 0; n < 4; n++) {
            int colA = 8 * n + cc;
            if (L0) {
                int jA = base + colA, jB = jA + 1;
                int dA0 = i0 - jA, dB0 = dA0 - 1;
                int dA1 = dA0 + 8, dB1 = dA1 - 1;
                s[n][0] = (jA >= 0 && (unsigned)dA0 < WW) ? fmaf(s[n][0], scale, -gamma * (float)dA0) : NEGV;
                s[n][1] = (jB >= 0 && (unsigned)dB0 < WW) ? fmaf(s[n][1], scale, -gamma * (float)dB0) : NEGV;
                s[n][2] = (jA >= 0 && (unsigned)dA1 < WW) ? fmaf(s[n][2], scale, -gamma * (float)dA1) : NEGV;
                s[n][3] = (jB >= 0 && (unsigned)dB1 < WW) ? fmaf(s[n][3], scale, -gamma * (float)dB1) : NEGV;
            } else {
                int jlA = (base + colA + 1) * S - 1;
                int jlB = jlA + S;
                int dA0 = i0 - jlA, dB0 = i0 - jlB;
                int dA1 = dA0 + 8, dB1 = dB0 + 8;
                s[n][0] = (dA0 >= WW) ? fmaf(s[n][0], scale, -gamma * (float)dA0) : NEGV;
                s[n][1] = (dB0 >= WW) ? fmaf(s[n][1], scale, -gamma * (float)dB0) : NEGV;
                s[n][2] = (dA1 >= WW) ? fmaf(s[n][2], scale, -gamma * (float)dA1) : NEGV;
                s[n][3] = (dB1 >= WW) ? fmaf(s[n][3], scale, -gamma * (float)dB1) : NEGV;
            }
        }

        // ---- online softmax ----
        float ml0 = s[0][0], ml1 = s[0][2];
#pragma unroll
        for (int n = 0; n < 4; n++) {
            ml0 = fmaxf(ml0, fmaxf(s[n][0], s[n][1]));
            ml1 = fmaxf(ml1, fmaxf(s[n][2], s[n][3]));
        }
        ml0 = fmaxf(ml0, __shfl_xor_sync(0xffffffffu, ml0, 1));
        ml0 = fmaxf(ml0, __shfl_xor_sync(0xffffffffu, ml0, 2));
        ml1 = fmaxf(ml1, __shfl_xor_sync(0xffffffffu, ml1, 1));
        ml1 = fmaxf(ml1, __shfl_xor_sync(0xffffffffu, ml1, 2));
        float nm0 = fmaxf(m0, ml0), nm1 = fmaxf(m1, ml1);
        float e0 = __expf(m0 - nm0), e1 = __expf(m1 - nm1);
        m0 = nm0; m1 = nm1;
        float sum0 = 0.f, sum1 = 0.f;
#pragma unroll
        for (int n = 0; n < 4; n++) {
            s[n][0] = __expf(s[n][0] - nm0); sum0 += s[n][0];
            s[n][1] = __expf(s[n][1] - nm0); sum0 += s[n][1];
            s[n][2] = __expf(s[n][2] - nm1); sum1 += s[n][2];
            s[n][3] = __expf(s[n][3] - nm1); sum1 += s[n][3];
        }
        l0 = fmaf(l0, e0, sum0);
        l1 = fmaf(l1, e1, sum1);
        if (!__all_sync(0xffffffffu, (e0 == 1.f) && (e1 == 1.f))) {
#pragma unroll
            for (int n = 0; n < 8; n++) {
                O[n][0] *= e0; O[n][1] *= e0; O[n][2] *= e1; O[n][3] *= e1;
            }
        }

        // ---- O += P V : 2 k-steps x 8 n-steps x 3 MMA (no shuffle repack) ----
#pragma unroll
        for (int kt = 0; kt < 2; kt++) {
            u32 Ah[4], Al[4];
            split2(s[2 * kt][0],     s[2 * kt][1],     Ah[0], Al[0]);
            split2(s[2 * kt][2],     s[2 * kt][3],     Ah[1], Al[1]);
            split2(s[2 * kt + 1][0], s[2 * kt + 1][1], Ah[2], Al[2]);
            split2(s[2 * kt + 1][2], s[2 * kt + 1][3], Ah[3], Al[3]);
#pragma unroll
            for (int nb = 0; nb < 8; nb++) {
                const u32* ph = vh + (nb * 8 + g) * RSV + c;
                const u32* pl = vl + (nb * 8 + g) * RSV + c;
                u32 bh0 = ph[8 * kt], bh1 = ph[8 * kt + 4];
                u32 bl0 = pl[8 * kt], bl1 = pl[8 * kt + 4];
                mma_bf16(O[nb][0], O[nb][1], O[nb][2], O[nb][3],
                         Ah[0], Ah[1], Ah[2], Ah[3], bh0, bh1);
                mma_bf16(O[nb][0], O[nb][1], O[nb][2], O[nb][3],
                         Ah[0], Ah[1], Ah[2], Ah[3], bl0, bl1);
                mma_bf16(O[nb][0], O[nb][1], O[nb][2], O[nb][3],
                         Al[0], Al[1], Al[2], Al[3], bh0, bh1);
            }
        }
    };

    // ================= Level 0: sliding window, nearest-first =================
    {
        const u16* khg = g_kh0 + (size_t)h * NN * DD;
        const u16* klg = g_kl0 + (size_t)h * NN * DD;
        const u16* vhg = g_vh0 + (size_t)h * DD * NN;
        const u16* vlg = g_vl0 + (size_t)h * DD * NN;
        prefetch_planes(skh[0], skl[0], svh[0], svl[0],
                        khg, klg, vhg, vlg, NN, qs + 128 - 32, tid);
#pragma unroll 1
        for (int it = 0; it < 8; it++) {
            cp_wait_all();
            __syncthreads();
            if (it + 1 < 8)
                prefetch_planes(skh[(it + 1) & 1], skl[(it + 1) & 1],
                                svh[(it + 1) & 1], svl[(it + 1) & 1],
                                khg, klg, vhg, vlg, NN,
                                qs + 128 - (it + 2) * 32, tid);
            int tb = qs + 128 - (it + 1) * 32;
            bool skip = (tb > r0 + 15) || (tb + 31 < r0 - (WW - 1));
            if (!skip)
                do_tile(skh[it & 1], skl[it & 1], svh[it & 1], svl[it & 1],
                        true, tb, 1, gm0);
        }
    }

    // ================= Levels 1..3: pooled chunks, nearest-first =================
#pragma unroll 1
    for (int lvl = 1; lvl <= 3; lvl++) {
        const u16 *khg, *klg, *vhg, *vlg; int C, S; float gamma;
        if (lvl == 1) {
            khg = g_kh1 + (size_t)h * 1024 * DD; klg = g_kl1 + (size_t)h * 1024 * DD;
            vhg = g_vh1 + (size_t)h * DD * 1024; vlg = g_vl1 + (size_t)h * DD * 1024;
            C = 1024; S = 8; gamma = gm1;
        } else if (lvl == 2) {
            khg = g_kh2 + (size_t)h * 128 * DD;  klg = g_kl2 + (size_t)h * 128 * DD;
            vhg = g_vh2 + (size_t)h * DD * 128;  vlg = g_vl2 + (size_t)h * DD * 128;
            C = 128; S = 64; gamma = gm2;
        } else {
            khg = g_kh3 + (size_t)h * 16 * DD;   klg = g_kl3 + (size_t)h * 16 * DD;
            vhg = g_vh3 + (size_t)h * DD * 16;   vlg = g_vl3 + (size_t)h * DD * 16;
            C = 16; S = 512; gamma = gm3;
        }
        int cmax = qs / S - 1;                 // block-level max visible chunk
        if (cmax < 0) continue;
        int nt = cmax / 32 + 1;
        int cwmax = (r0 >= 112 + S) ? ((r0 - 112) / S - 1) : -1;  // warp-level
        __syncthreads();                        // previous buffers done
        prefetch_planes(skh[0], skl[0], svh[0], svl[0],
                        khg, klg, vhg, vlg, C, (nt - 1) * 32, tid);
#pragma unroll 1
        for (int it = 0; it < nt; it++) {
            cp_wait_all();
            __syncthreads();
            if (it + 1 < nt)
                prefetch_planes(skh[(it + 1) & 1], skl[(it + 1) & 1],
                                svh[(it + 1) & 1], svl[(it + 1) & 1],
                                khg, klg, vhg, vlg, C, (nt - 2 - it) * 32, tid);
            int cb = (nt - 1 - it) * 32;
            if (cb <= cwmax)
                do_tile(skh[it & 1], skl[it & 1], svh[it & 1], svl[it & 1],
                        false, cb, S, gamma);
        }
    }

    // ================= epilogue: out = O / clip(l, 1e-8) =================
    l0 += __shfl_xor_sync(0xffffffffu, l0, 1);
    l0 += __shfl_xor_sync(0xffffffffu, l0, 2);
    l1 += __shfl_xor_sync(0xffffffffu, l1, 1);
    l1 += __shfl_xor_sync(0xffffffffu, l1, 2);
    float inv0 = 1.0f / fmaxf(l0, 1e-8f);
    float inv1 = 1.0f / fmaxf(l1, 1e-8f);
    float* o0p = out + ((size_t)h * NN + i0) * DD;
    float* o1p = out + ((size_t)h * NN + i1) * DD;
#pragma unroll
    for (int n = 0; n < 8; n++) {
        float2 w0 = make_float2(O[n][0] * inv0, O[n][1] * inv0);
        float2 w1 = make_float2(O[n][2] * inv1, O[n][3] * inv1);
        *reinterpret_cast<float2*>(o0p + 8 * n + cc) = w0;
        *reinterpret_cast<float2*>(o1p + 8 * n + cc) = w1;
    }
}

// ---------------- launch ----------------
extern "C" void kernel_launch(void* const* d_in, const int* in_sizes, int n_in,
                              void* d_out, int out_size) {
    const float* q      = (const float*)d_in[0];
    const float* k      = (const float*)d_in[1];
    const float* v      = (const float*)d_in[2];
    const float* gammas = (const float*)d_in[3];
    float* out = (float*)d_out;

    u16 *kh0, *kl0, *vh0, *vl0, *kh1, *kl1, *vh1, *vl1;
    u16 *kh2, *kl2, *vh2, *vl2, *kh3, *kl3, *vh3, *vl3;
    float *k1, *v1, *k2, *v2, *k3, *v3;
    cudaGetSymbolAddress((void**)&kh0, g_kh0); cudaGetSymbolAddress((void**)&kl0, g_kl0);
    cudaGetSymbolAddress((void**)&vh0, g_vh0); cudaGetSymbolAddress((void**)&vl0, g_vl0);
    cudaGetSymbolAddress((void**)&kh1, g_kh1); cudaGetSymbolAddress((void**)&kl1, g_kl1);
    cudaGetSymbolAddress((void**)&vh1, g_vh1); cudaGetSymbolAddress((void**)&vl1, g_vl1);
    cudaGetSymbolAddress((void**)&kh2, g_kh2); cudaGetSymbolAddress((void**)&kl2, g_kl2);
    cudaGetSymbolAddress((void**)&vh2, g_vh2); cudaGetSymbolAddress((void**)&vl2, g_vl2);
    cudaGetSymbolAddress((void**)&kh3, g_kh3); cudaGetSymbolAddress((void**)&kl3, g_kl3);
    cudaGetSymbolAddress((void**)&vh3, g_vh3); cudaGetSymbolAddress((void**)&vl3, g_vl3);
    cudaGetSymbolAddress((void**)&k1, g_k1);   cudaGetSymbolAddress((void**)&v1, g_v1);
    cudaGetSymbolAddress((void**)&k2, g_k2);   cudaGetSymbolAddress((void**)&v2, g_v2);
    cudaGetSymbolAddress((void**)&k3, g_k3);   cudaGetSymbolAddress((void**)&v3, g_v3);

    split_tr_kernel<<<dim3(NN / 32, HH), 256>>>(k, v, NN, kh0, kl0, vh0, vl0);
    pool1_kernel<<<(HH * 1024 * DD + 255) / 256, 256>>>(k, v);
    split_tr_kernel<<<dim3(1024 / 32, HH), 256>>>(k1, v1, 1024, kh1, kl1, vh1, vl1);
    pool2_kernel<<<(HH * 128 * DD + 255) / 256, 256>>>();
    split_tr_kernel<<<dim3(128 / 32, HH), 256>>>(k2, v2, 128, kh2, kl2, vh2, vl2);
    pool3_kernel<<<(HH * 16 * DD + 255) / 256, 256>>>();
    split_tr_kernel<<<dim3(1, HH), 256>>>(k3, v3, 16, kh3, kl3, vh3, vl3);

    dim3 grid(NN / 128, HH);
    attn_kernel<<<grid, 256>>>(q, gammas, out);
}

// round 12
// speedup vs baseline: 4.6228x; 1.3888x over previous
#include <cuda_runtime.h>
#include <cuda_bf16.h>

#define HH 16
#define NN 8192
#define DD 64
#define WW 128
#define NEGV (-1e30f)
#define RSK 36   // words per K-plane smem row (32 data + 4 pad)
#define RSV 20   // words per V-plane smem row (16 data + 4 pad)

typedef unsigned short u16;
typedef unsigned int u32;

// ---------------- fp32 pooled intermediates ----------------
__device__ float g_k1[HH * 1024 * DD];
__device__ float g_v1[HH * 1024 * DD];
__device__ float g_k2[HH * 128 * DD];
__device__ float g_v2[HH * 128 * DD];
__device__ float g_k3[HH * 16 * DD];
__device__ float g_v3[HH * 16 * DD];

// ---------------- bf16 hi/lo split planes ----------------
// K planes: [h][key][d] (d-major). V planes: [h][d][key] (transposed).
__device__ u16 g_kh0[HH * NN * DD],   g_kl0[HH * NN * DD];
__device__ u16 g_vh0[HH * DD * NN],   g_vl0[HH * DD * NN];
__device__ u16 g_kh1[HH * 1024 * DD], g_kl1[HH * 1024 * DD];
__device__ u16 g_vh1[HH * DD * 1024], g_vl1[HH * DD * 1024];
__device__ u16 g_kh2[HH * 128 * DD],  g_kl2[HH * 128 * DD];
__device__ u16 g_vh2[HH * DD * 128],  g_vl2[HH * DD * 128];
__device__ u16 g_kh3[HH * 16 * DD],   g_kl3[HH * 16 * DD];
__device__ u16 g_vh3[HH * DD * 16],   g_vl3[HH * DD * 16];

// ---------------- helpers ----------------
__device__ __forceinline__ void mma_bf16(
    float& d0, float& d1, float& d2, float& d3,
    u32 a0, u32 a1, u32 a2, u32 a3, u32 b0, u32 b1)
{
    asm volatile(
        "mma.sync.aligned.m16n8k16.row.col.f32.bf16.bf16.f32 "
        "{%0,%1,%2,%3}, {%4,%5,%6,%7}, {%8,%9}, {%0,%1,%2,%3};\n"
        : "+f"(d0), "+f"(d1), "+f"(d2), "+f"(d3)
        : "r"(a0), "r"(a1), "r"(a2), "r"(a3), "r"(b0), "r"(b1));
}

// pack two f32 -> bf16x2 (e0 in low 16 bits)
__device__ __forceinline__ u32 packbf(float e0, float e1) {
    u32 r; asm("cvt.rn.bf16x2.f32 %0, %1, %2;" : "=r"(r) : "f"(e1), "f"(e0));
    return r;
}
// split pair into hi bf16x2 + lo bf16x2 (error-free residual)
__device__ __forceinline__ void split2(float x0, float x1, u32& hi, u32& lo) {
    hi = packbf(x0, x1);
    float h0 = __uint_as_float(hi << 16);
    float h1 = __uint_as_float(hi & 0xffff0000u);
    lo = packbf(x0 - h0, x1 - h1);
}

__device__ __forceinline__ void cp16(const void* smem_dst, const void* gsrc) {
    unsigned sa = (unsigned)__cvta_generic_to_shared(smem_dst);
    asm volatile("cp.async.cg.shared.global [%0], [%1], 16;" :: "r"(sa), "l"(gsrc));
}
__device__ __forceinline__ void cp_commit() {
    asm volatile("cp.async.commit_group;" ::: "memory");
}
__device__ __forceinline__ void cp_wait_all() {
    asm volatile("cp.async.wait_group 0;" ::: "memory");
}

// ---------------- fused split + transpose + pool kernel ----------------
// Per block: 32-key x 64-d fp32 tile of one head staged in smem, then:
//   - K hi/lo planes written d-major (same layout as source)
//   - V hi/lo planes written transposed [d][key]
//   - optional: next level's pooled means (4 chunks of 8 keys) in fp32
__global__ void fuse_kernel(const float* __restrict__ ksrc,
                            const float* __restrict__ vsrc, int C,
                            u16* __restrict__ khi, u16* __restrict__ klo,
                            u16* __restrict__ vhi, u16* __restrict__ vlo,
                            float* __restrict__ kpool, float* __restrict__ vpool)
{
    __shared__ float skf[32][65], svf[32][65];
    int h = blockIdx.y, k0 = blockIdx.x * 32;
    int tid = threadIdx.x;

    // stage tile (zero-fill rows beyond C)
#pragma unroll
    for (int it = 0; it < 2; it++) {
        int e = tid + it * 256;            // [0, 512)
        int row = e >> 4, f4 = e & 15;
        float4 a = make_float4(0.f, 0.f, 0.f, 0.f), b = a;
        if (k0 + row < C) {
            a = reinterpret_cast<const float4*>(ksrc + ((size_t)h * C + k0 + row) * DD)[f4];
            b = reinterpret_cast<const float4*>(vsrc + ((size_t)h * C + k0 + row) * DD)[f4];
        }
        skf[row][f4 * 4 + 0] = a.x; skf[row][f4 * 4 + 1] = a.y;
        skf[row][f4 * 4 + 2] = a.z; skf[row][f4 * 4 + 3] = a.w;
        svf[row][f4 * 4 + 0] = b.x; svf[row][f4 * 4 + 1] = b.y;
        svf[row][f4 * 4 + 2] = b.z; svf[row][f4 * 4 + 3] = b.w;
    }
    __syncthreads();

    // K splits (d-major, packed u32 writes)
#pragma unroll
    for (int it = 0; it < 4; it++) {
        int idx = tid + it * 256;          // [0, 1024)
        int key = idx >> 5, dp = (idx & 31) * 2;
        if (k0 + key < C) {
            u32 hi, lo;
            split2(skf[key][dp], skf[key][dp + 1], hi, lo);
            size_t w = ((size_t)h * C + k0 + key) * 32 + (idx & 31);
            reinterpret_cast<u32*>(khi)[w] = hi;
            reinterpret_cast<u32*>(klo)[w] = lo;
        }
    }

    // V splits (transposed [d][key], packed over key pairs)
#pragma unroll
    for (int it = 0; it < 4; it++) {
        int idx = tid + it * 256;          // [0, 1024)
        int d = idx >> 4, kp = (idx & 15) * 2;
        if (k0 + kp < C) {
            u32 hi, lo;
            split2(svf[kp][d], svf[kp + 1][d], hi, lo);
            size_t w = (((size_t)h * DD + d) * C + k0 + kp) >> 1;
            reinterpret_cast<u32*>(vhi)[w] = hi;
            reinterpret_cast<u32*>(vlo)[w] = lo;
        }
    }

    // pooled means for next level (4 chunks x 64 d), exact fp32 ascending sum
    if (kpool != nullptr) {
        int chunk = tid >> 6, d = tid & 63;
        float sk = 0.f, sv = 0.f;
#pragma unroll
        for (int r = 0; r < 8; r++) {
            sk += skf[chunk * 8 + r][d];
            sv += svf[chunk * 8 + r][d];
        }
        size_t w = ((size_t)h * (C / 8) + (k0 >> 3) + chunk) * DD + d;
        kpool[w] = sk * 0.125f;
        vpool[w] = sv * 0.125f;
    }
}

// ---------------- tile prefetch (all four planes) ----------------
__device__ __forceinline__ void prefetch_planes(
    u32* khs, u32* kls, u32* vhs, u32* vls,
    const u16* __restrict__ khg, const u16* __restrict__ klg,
    const u16* __restrict__ vhg, const u16* __restrict__ vlg,
    int C, int tb, int tid)
{
    {   // K planes: 32 rows x 128B
        int row = tid >> 3, ch = tid & 7;
        int r = tb + row;
        r = r < 0 ? 0 : (r > C - 1 ? C - 1 : r);
        size_t so = (size_t)r * DD + ch * 8;
        cp16(khs + row * RSK + ch * 4, khg + so);
        cp16(kls + row * RSK + ch * 4, klg + so);
    }
    {   // V planes (transposed): 64 d-rows x 64B
        int d = tid >> 2, ch = tid & 3;
        int k0 = tb + ch * 8;
        k0 = k0 < 0 ? 0 : (k0 > C - 8 ? C - 8 : k0);
        size_t so = (size_t)d * C + k0;
        cp16(vhs + d * RSV + ch * 4, vhg + so);
        cp16(vls + d * RSV + ch * 4, vlg + so);
    }
    cp_commit();
}

// ---------------- FA2 bf16-split attention ----------------
// CTA = 128 queries x 1 head; 8 warps x 16 rows. m16n8k16 bf16, 3-term split:
// Ah*Bh + Ah*Bl + Al*Bh. ALiBi horizon cut: chunks with gamma*dist > 40
// contribute < e^-28 relative and are skipped at tile granularity.

__global__ void __launch_bounds__(256, 2) attn_kernel(
    const float* __restrict__ q, const float* __restrict__ gammas,
    float* __restrict__ out)
{
    __shared__ u32 skh[2][32 * RSK], skl[2][32 * RSK];
    __shared__ u32 svh[2][DD * RSV], svl[2][DD * RSV];

    int h = blockIdx.y;
    int qtile = (int)(gridDim.x - 1u - blockIdx.x);   // heavy tiles first
    int qs = qtile * 128;
    int tid = threadIdx.x;
    int warp = tid >> 5, lane = tid & 31;
    int r0 = qs + warp * 16;
    int g = lane >> 2, c = lane & 3;
    int cc = 2 * c;
    int i0 = r0 + g, i1 = i0 + 8;

    // Q split once: qh/ql[ks][0..3] (bf16x2 fragments for 4 k16-steps)
    u32 qh[4][4], ql[4][4];
    {
        const float* q0p = q + ((size_t)h * NN + i0) * DD;
        const float* q1p = q + ((size_t)h * NN + i1) * DD;
#pragma unroll
        for (int ks = 0; ks < 4; ks++) {
            split2(q0p[16 * ks + cc],     q0p[16 * ks + cc + 1], qh[ks][0], ql[ks][0]);
            split2(q1p[16 * ks + cc],     q1p[16 * ks + cc + 1], qh[ks][1], ql[ks][1]);
            split2(q0p[16 * ks + cc + 8], q0p[16 * ks + cc + 9], qh[ks][2], ql[ks][2]);
            split2(q1p[16 * ks + cc + 8], q1p[16 * ks + cc + 9], qh[ks][3], ql[ks][3]);
        }
    }

    float m0 = NEGV, m1 = NEGV, l0 = 0.f, l1 = 0.f;
    float O[8][4];
#pragma unroll
    for (int n = 0; n < 8; n++) { O[n][0] = O[n][1] = O[n][2] = O[n][3] = 0.f; }

    float gm0 = __ldg(&gammas[0]), gm1 = __ldg(&gammas[1]);
    float gm2 = __ldg(&gammas[2]), gm3 = __ldg(&gammas[3]);
    const float scale = 0.125f;

    auto do_tile = [&](const u32* kh, const u32* kl, const u32* vh, const u32* vl,
                       bool L0, int base, int S, float gamma) {
        float s[4][4];
#pragma unroll
        for (int n = 0; n < 4; n++) { s[n][0] = s[n][1] = s[n][2] = s[n][3] = 0.f; }

        // ---- QK^T: 4 n-steps x 4 k-steps x 3 MMA ----
#pragma unroll
        for (int nb = 0; nb < 4; nb++) {
            const u32* ph = kh + (nb * 8 + g) * RSK + c;
            const u32* pl = kl + (nb * 8 + g) * RSK + c;
#pragma unroll
            for (int ks = 0; ks < 4; ks++) {
                u32 bh0 = ph[8 * ks], bh1 = ph[8 * ks + 4];
                u32 bl0 = pl[8 * ks], bl1 = pl[8 * ks + 4];
                mma_bf16(s[nb][0], s[nb][1], s[nb][2], s[nb][3],
                         qh[ks][0], qh[ks][1], qh[ks][2], qh[ks][3], bh0, bh1);
                mma_bf16(s[nb][0], s[nb][1], s[nb][2], s[nb][3],
                         qh[ks][0], qh[ks][1], qh[ks][2], qh[ks][3], bl0, bl1);
                mma_bf16(s[nb][0], s[nb][1], s[nb][2], s[nb][3],
                         ql[ks][0], ql[ks][1], ql[ks][2], ql[ks][3], bh0, bh1);
            }
        }

        // ---- mask + ALiBi bias (C-frag: cols 8n+2c, 8n+2c+1; rows i0/i1) ----
#pragma unroll
        for (int n = 0; n < 4; n++) {
            int colA = 8 * n + cc;
            if (L0) {
                int jA = base + colA, jB = jA + 1;
                int dA0 = i0 - jA, dB0 = dA0 - 1;
                int dA1 = dA0 + 8, dB1 = dA1 - 1;
                s[n][0] = (jA >= 0 && (unsigned)dA0 < WW) ? fmaf(s[n][0], scale, -gamma * (float)dA0) : NEGV;
                s[n][1] = (jB >= 0 && (unsigned)dB0 < WW) ? fmaf(s[n][1], scale, -gamma * (float)dB0) : NEGV;
                s[n][2] = (jA >= 0 && (unsigned)dA1 < WW) ? fmaf(s[n][2], scale, -gamma * (float)dA1) : NEGV;
                s[n][3] = (jB >= 0 && (unsigned)dB1 < WW) ? fmaf(s[n][3], scale, -gamma * (float)dB1) : NEGV;
            } else {
                int jlA = (base + colA + 1) * S - 1;
                int jlB = jlA + S;
                int dA0 = i0 - jlA, dB0 = i0 - jlB;
                int dA1 = dA0 + 8, dB1 = dB0 + 8;
                s[n][0] = (dA0 >= WW) ? fmaf(s[n][0], scale, -gamma * (float)dA0) : NEGV;
                s[n][1] = (dB0 >= WW) ? fmaf(s[n][1], scale, -gamma * (float)dB0) : NEGV;
                s[n][2] = (dA1 >= WW) ? fmaf(s[n][2], scale, -gamma * (float)dA1) : NEGV;
                s[n][3] = (dB1 >= WW) ? fmaf(s[n][3], scale, -gamma * (float)dB1) : NEGV;
            }
        }

        // ---- online softmax ----
        float ml0 = s[0][0], ml1 = s[0][2];
#pragma unroll
        for (int n = 0; n < 4; n++) {
            ml0 = fmaxf(ml0, fmaxf(s[n][0], s[n][1]));
            ml1 = fmaxf(ml1, fmaxf(s[n][2], s[n][3]));
        }
        ml0 = fmaxf(ml0, __shfl_xor_sync(0xffffffffu, ml0, 1));
        ml0 = fmaxf(ml0, __shfl_xor_sync(0xffffffffu, ml0, 2));
        ml1 = fmaxf(ml1, __shfl_xor_sync(0xffffffffu, ml1, 1));
        ml1 = fmaxf(ml1, __shfl_xor_sync(0xffffffffu, ml1, 2));
        float nm0 = fmaxf(m0, ml0), nm1 = fmaxf(m1, ml1);
        float e0 = __expf(m0 - nm0), e1 = __expf(m1 - nm1);
        m0 = nm0; m1 = nm1;
        float sum0 = 0.f, sum1 = 0.f;
#pragma unroll
        for (int n = 0; n < 4; n++) {
            s[n][0] = __expf(s[n][0] - nm0); sum0 += s[n][0];
            s[n][1] = __expf(s[n][1] - nm0); sum0 += s[n][1];
            s[n][2] = __expf(s[n][2] - nm1); sum1 += s[n][2];
            s[n][3] = __expf(s[n][3] - nm1); sum1 += s[n][3];
        }
        l0 = fmaf(l0, e0, sum0);
        l1 = fmaf(l1, e1, sum1);
        if (!__all_sync(0xffffffffu, (e0 == 1.f) && (e1 == 1.f))) {
#pragma unroll
            for (int n = 0; n < 8; n++) {
                O[n][0] *= e0; O[n][1] *= e0; O[n][2] *= e1; O[n][3] *= e1;
            }
        }

        // ---- O += P V : 2 k-steps x 8 n-steps x 3 MMA (no shuffle repack) ----
#pragma unroll
        for (int kt = 0; kt < 2; kt++) {
            u32 Ah[4], Al[4];
            split2(s[2 * kt][0],     s[2 * kt][1],     Ah[0], Al[0]);
            split2(s[2 * kt][2],     s[2 * kt][3],     Ah[1], Al[1]);
            split2(s[2 * kt + 1][0], s[2 * kt + 1][1], Ah[2], Al[2]);
            split2(s[2 * kt + 1][2], s[2 * kt + 1][3], Ah[3], Al[3]);
#pragma unroll
            for (int nb = 0; nb < 8; nb++) {
                const u32* ph = vh + (nb * 8 + g) * RSV + c;
                const u32* pl = vl + (nb * 8 + g) * RSV + c;
                u32 bh0 = ph[8 * kt], bh1 = ph[8 * kt + 4];
                u32 bl0 = pl[8 * kt], bl1 = pl[8 * kt + 4];
                mma_bf16(O[nb][0], O[nb][1], O[nb][2], O[nb][3],
                         Ah[0], Ah[1], Ah[2], Ah[3], bh0, bh1);
                mma_bf16(O[nb][0], O[nb][1], O[nb][2], O[nb][3],
                         Ah[0], Ah[1], Ah[2], Ah[3], bl0, bl1);
                mma_bf16(O[nb][0], O[nb][1], O[nb][2], O[nb][3],
                         Al[0], Al[1], Al[2], Al[3], bh0, bh1);
            }
        }
    };

    // ================= Level 0: sliding window, nearest-first =================
    {
        const u16* khg = g_kh0 + (size_t)h * NN * DD;
        const u16* klg = g_kl0 + (size_t)h * NN * DD;
        const u16* vhg = g_vh0 + (size_t)h * DD * NN;
        const u16* vlg = g_vl0 + (size_t)h * DD * NN;
        prefetch_planes(skh[0], skl[0], svh[0], svl[0],
                        khg, klg, vhg, vlg, NN, qs + 128 - 32, tid);
#pragma unroll 1
        for (int it = 0; it < 8; it++) {
            cp_wait_all();
            __syncthreads();
            if (it + 1 < 8)
                prefetch_planes(skh[(it + 1) & 1], skl[(it + 1) & 1],
                                svh[(it + 1) & 1], svl[(it + 1) & 1],
                                khg, klg, vhg, vlg, NN,
                                qs + 128 - (it + 2) * 32, tid);
            int tb = qs + 128 - (it + 1) * 32;
            bool skip = (tb > r0 + 15) || (tb + 31 < r0 - (WW - 1));
            if (!skip)
                do_tile(skh[it & 1], skl[it & 1], svh[it & 1], svl[it & 1],
                        true, tb, 1, gm0);
        }
    }

    // ================= Levels 1..3: pooled chunks, nearest-first =================
#pragma unroll 1
    for (int lvl = 1; lvl <= 3; lvl++) {
        const u16 *khg, *klg, *vhg, *vlg; int C, S; float gamma;
        if (lvl == 1) {
            khg = g_kh1 + (size_t)h * 1024 * DD; klg = g_kl1 + (size_t)h * 1024 * DD;
            vhg = g_vh1 + (size_t)h * DD * 1024; vlg = g_vl1 + (size_t)h * DD * 1024;
            C = 1024; S = 8; gamma = gm1;
        } else if (lvl == 2) {
            khg = g_kh2 + (size_t)h * 128 * DD;  klg = g_kl2 + (size_t)h * 128 * DD;
            vhg = g_vh2 + (size_t)h * DD * 128;  vlg = g_vl2 + (size_t)h * DD * 128;
            C = 128; S = 64; gamma = gm2;
        } else {
            khg = g_kh3 + (size_t)h * 16 * DD;   klg = g_kl3 + (size_t)h * 16 * DD;
            vhg = g_vh3 + (size_t)h * DD * 16;   vlg = g_vl3 + (size_t)h * DD * 16;
            C = 16; S = 512; gamma = gm3;
        }
        int cmax = qs / S - 1;                 // block-level max visible chunk
        if (cmax < 0) continue;
        int nt = cmax / 32 + 1;
        int cwmax = (r0 >= 112 + S) ? ((r0 - 112) / S - 1) : -1;  // warp-level
        // ALiBi horizon: chunks with gamma*dist > 40 are machine-negligible.
        int dcut = (int)(40.0f / gamma);
        int cmin = 0;
        if (qs + 1 > dcut) cmin = (qs + 1 - dcut + S - 1) / S - 1;
        if (cmin < 0) cmin = 0;
        int nte = nt - (cmin >> 5);            // tiles to actually process
        if (nte <= 0) continue;
        __syncthreads();                        // previous buffers done
        prefetch_planes(skh[0], skl[0], svh[0], svl[0],
                        khg, klg, vhg, vlg, C, (nt - 1) * 32, tid);
#pragma unroll 1
        for (int it = 0; it < nte; it++) {
            cp_wait_all();
            __syncthreads();
            if (it + 1 < nte)
                prefetch_planes(skh[(it + 1) & 1], skl[(it + 1) & 1],
                                svh[(it + 1) & 1], svl[(it + 1) & 1],
                                khg, klg, vhg, vlg, C, (nt - 2 - it) * 32, tid);
            int cb = (nt - 1 - it) * 32;
            if (cb <= cwmax && (r0 - ((cb + 32) * S - 1)) <= dcut)
                do_tile(skh[it & 1], skl[it & 1], svh[it & 1], svl[it & 1],
                        false, cb, S, gamma);
        }
    }

    // ================= epilogue: out = O / clip(l, 1e-8) =================
    l0 += __shfl_xor_sync(0xffffffffu, l0, 1);
    l0 += __shfl_xor_sync(0xffffffffu, l0, 2);
    l1 += __shfl_xor_sync(0xffffffffu, l1, 1);
    l1 += __shfl_xor_sync(0xffffffffu, l1, 2);
    float inv0 = 1.0f / fmaxf(l0, 1e-8f);
    float inv1 = 1.0f / fmaxf(l1, 1e-8f);
    float* o0p = out + ((size_t)h * NN + i0) * DD;
    float* o1p = out + ((size_t)h * NN + i1) * DD;
#pragma unroll
    for (int n = 0; n < 8; n++) {
        float2 w0 = make_float2(O[n][0] * inv0, O[n][1] * inv0);
        float2 w1 = make_float2(O[n][2] * inv1, O[n][3] * inv1);
        *reinterpret_cast<float2*>(o0p + 8 * n + cc) = w0;
        *reinterpret_cast<float2*>(o1p + 8 * n + cc) = w1;
    }
}

// ---------------- launch ----------------
extern "C" void kernel_launch(void* const* d_in, const int* in_sizes, int n_in,
                              void* d_out, int out_size) {
    const float* q      = (const float*)d_in[0];
    const float* k      = (const float*)d_in[1];
    const float* v      = (const float*)d_in[2];
    const float* gammas = (const float*)d_in[3];
    float* out = (float*)d_out;

    u16 *kh0, *kl0, *vh0, *vl0, *kh1, *kl1, *vh1, *vl1;
    u16 *kh2, *kl2, *vh2, *vl2, *kh3, *kl3, *vh3, *vl3;
    float *k1, *v1, *k2, *v2, *k3, *v3;
    cudaGetSymbolAddress((void**)&kh0, g_kh0); cudaGetSymbolAddress((void**)&kl0, g_kl0);
    cudaGetSymbolAddress((void**)&vh0, g_vh0); cudaGetSymbolAddress((void**)&vl0, g_vl0);
    cudaGetSymbolAddress((void**)&kh1, g_kh1); cudaGetSymbolAddress((void**)&kl1, g_kl1);
    cudaGetSymbolAddress((void**)&vh1, g_vh1); cudaGetSymbolAddress((void**)&vl1, g_vl1);
    cudaGetSymbolAddress((void**)&kh2, g_kh2); cudaGetSymbolAddress((void**)&kl2, g_kl2);
    cudaGetSymbolAddress((void**)&vh2, g_vh2); cudaGetSymbolAddress((void**)&vl2, g_vl2);
    cudaGetSymbolAddress((void**)&kh3, g_kh3); cudaGetSymbolAddress((void**)&kl3, g_kl3);
    cudaGetSymbolAddress((void**)&vh3, g_vh3); cudaGetSymbolAddress((void**)&vl3, g_vl3);
    cudaGetSymbolAddress((void**)&k1, g_k1);   cudaGetSymbolAddress((void**)&v1, g_v1);
    cudaGetSymbolAddress((void**)&k2, g_k2);   cudaGetSymbolAddress((void**)&v2, g_v2);
    cudaGetSymbolAddress((void**)&k3, g_k3);   cudaGetSymbolAddress((void**)&v3, g_v3);

    // fused: split level-l planes + pool level-(l+1) means, one pass each
    fuse_kernel<<<dim3(NN / 32, HH), 256>>>(k, v, NN, kh0, kl0, vh0, vl0, k1, v1);
    fuse_kernel<<<dim3(1024 / 32, HH), 256>>>(k1, v1, 1024, kh1, kl1, vh1, vl1, k2, v2);
    fuse_kernel<<<dim3(128 / 32, HH), 256>>>(k2, v2, 128, kh2, kl2, vh2, vl2, k3, v3);
    fuse_kernel<<<dim3(1, HH), 256>>>(k3, v3, 16, kh3, kl3, vh3, vl3, nullptr, nullptr);

    dim3 grid(NN / 128, HH);
    attn_kernel<<<grid, 256>>>(q, gammas, out);
}

// round 14
// speedup vs baseline: 5.1962x; 1.1240x over previous
#include <cuda_runtime.h>
#include <cuda_bf16.h>

#define HH 16
#define NN 8192
#define DD 64
#define WW 128
#define NEGV (-1e30f)
#define RS 36          // words per smem plane row (32 data + 4 pad)
#define PLANE 2304     // u32 per plane (64 rows * 36)
#define BUFU 9216      // u32 per buffer (4 planes)
#define SMEM_BYTES (2 * BUFU * 4)

typedef unsigned short u16;
typedef unsigned int u32;

// ---------------- fp32 pooled intermediates ----------------
__device__ float g_k1[HH * 1024 * DD];
__device__ float g_v1[HH * 1024 * DD];
__device__ float g_k2[HH * 128 * DD];
__device__ float g_v2[HH * 128 * DD];
__device__ float g_k3[HH * 16 * DD];
__device__ float g_v3[HH * 16 * DD];

// ---------------- bf16 hi/lo split planes ----------------
// K planes: [h][key][d] (d-major). V planes: [h][d][key] (transposed).
__device__ u16 g_kh0[HH * NN * DD],   g_kl0[HH * NN * DD];
__device__ u16 g_vh0[HH * DD * NN],   g_vl0[HH * DD * NN];
__device__ u16 g_kh1[HH * 1024 * DD], g_kl1[HH * 1024 * DD];
__device__ u16 g_vh1[HH * DD * 1024], g_vl1[HH * DD * 1024];
__device__ u16 g_kh2[HH * 128 * DD],  g_kl2[HH * 128 * DD];
__device__ u16 g_vh2[HH * DD * 128],  g_vl2[HH * DD * 128];
__device__ u16 g_kh3[HH * 16 * DD],   g_kl3[HH * 16 * DD];
__device__ u16 g_vh3[HH * DD * 16],   g_vl3[HH * DD * 16];

// ---------------- helpers ----------------
__device__ __forceinline__ void mma_bf16(
    float& d0, float& d1, float& d2, float& d3,
    u32 a0, u32 a1, u32 a2, u32 a3, u32 b0, u32 b1)
{
    asm volatile(
        "mma.sync.aligned.m16n8k16.row.col.f32.bf16.bf16.f32 "
        "{%0,%1,%2,%3}, {%4,%5,%6,%7}, {%8,%9}, {%0,%1,%2,%3};\n"
        : "+f"(d0), "+f"(d1), "+f"(d2), "+f"(d3)
        : "r"(a0), "r"(a1), "r"(a2), "r"(a3), "r"(b0), "r"(b1));
}

__device__ __forceinline__ u32 packbf(float e0, float e1) {
    u32 r; asm("cvt.rn.bf16x2.f32 %0, %1, %2;" : "=r"(r) : "f"(e1), "f"(e0));
    return r;
}
__device__ __forceinline__ void split2(float x0, float x1, u32& hi, u32& lo) {
    hi = packbf(x0, x1);
    float h0 = __uint_as_float(hi << 16);
    float h1 = __uint_as_float(hi & 0xffff0000u);
    lo = packbf(x0 - h0, x1 - h1);
}

__device__ __forceinline__ void cp16(const void* smem_dst, const void* gsrc) {
    unsigned sa = (unsigned)__cvta_generic_to_shared(smem_dst);
    asm volatile("cp.async.cg.shared.global [%0], [%1], 16;" :: "r"(sa), "l"(gsrc));
}
__device__ __forceinline__ void cp_commit() {
    asm volatile("cp.async.commit_group;" ::: "memory");
}
__device__ __forceinline__ void cp_wait_all() {
    asm volatile("cp.async.wait_group 0;" ::: "memory");
}

// ---------------- fused split + transpose + pool kernel ----------------
__global__ void fuse_kernel(const float* __restrict__ ksrc,
                            const float* __restrict__ vsrc, int C,
                            u16* __restrict__ khi, u16* __restrict__ klo,
                            u16* __restrict__ vhi, u16* __restrict__ vlo,
                            float* __restrict__ kpool, float* __restrict__ vpool)
{
    __shared__ float skf[32][65], svf[32][65];
    int h = blockIdx.y, k0 = blockIdx.x * 32;
    int tid = threadIdx.x;
#pragma unroll
    for (int it = 0; it < 2; it++) {
        int e = tid + it * 256;
        int row = e >> 4, f4 = e & 15;
        float4 a = make_float4(0.f, 0.f, 0.f, 0.f), b = a;
        if (k0 + row < C) {
            a = reinterpret_cast<const float4*>(ksrc + ((size_t)h * C + k0 + row) * DD)[f4];
            b = reinterpret_cast<const float4*>(vsrc + ((size_t)h * C + k0 + row) * DD)[f4];
        }
        skf[row][f4 * 4 + 0] = a.x; skf[row][f4 * 4 + 1] = a.y;
        skf[row][f4 * 4 + 2] = a.z; skf[row][f4 * 4 + 3] = a.w;
        svf[row][f4 * 4 + 0] = b.x; svf[row][f4 * 4 + 1] = b.y;
        svf[row][f4 * 4 + 2] = b.z; svf[row][f4 * 4 + 3] = b.w;
    }
    __syncthreads();
#pragma unroll
    for (int it = 0; it < 4; it++) {
        int idx = tid + it * 256;
        int key = idx >> 5, dp = (idx & 31) * 2;
        if (k0 + key < C) {
            u32 hi, lo;
            split2(skf[key][dp], skf[key][dp + 1], hi, lo);
            size_t w = ((size_t)h * C + k0 + key) * 32 + (idx & 31);
            reinterpret_cast<u32*>(khi)[w] = hi;
            reinterpret_cast<u32*>(klo)[w] = lo;
        }
    }
#pragma unroll
    for (int it = 0; it < 4; it++) {
        int idx = tid + it * 256;
        int d = idx >> 4, kp = (idx & 15) * 2;
        if (k0 + kp < C) {
            u32 hi, lo;
            split2(svf[kp][d], svf[kp + 1][d], hi, lo);
            size_t w = (((size_t)h * DD + d) * C + k0 + kp) >> 1;
            reinterpret_cast<u32*>(vhi)[w] = hi;
            reinterpret_cast<u32*>(vlo)[w] = lo;
        }
    }
    if (kpool != nullptr) {
        int chunk = tid >> 6, d = tid & 63;
        float sk = 0.f, sv = 0.f;
#pragma unroll
        for (int r = 0; r < 8; r++) {
            sk += skf[chunk * 8 + r][d];
            sv += svf[chunk * 8 + r][d];
        }
        size_t w = ((size_t)h * (C / 8) + (k0 >> 3) + chunk) * DD + d;
        kpool[w] = sk * 0.125f;
        vpool[w] = sv * 0.125f;
    }
}

// ---------------- 64-key tile prefetch (all four planes) ----------------
__device__ __forceinline__ void prefetch64(
    u32* sm, int buf,
    const u16* __restrict__ khg, const u16* __restrict__ klg,
    const u16* __restrict__ vhg, const u16* __restrict__ vlg,
    int C, int tb, int tid)
{
    u32* kh = sm + buf * BUFU;
    u32* kl = kh + PLANE;
    u32* vh = kl + PLANE;
    u32* vl = vh + PLANE;
    // K planes: 64 key-rows x 128B (8 chunks of 16B each)
#pragma unroll
    for (int t = 0; t < 2; t++) {
        int e = tid + t * 256;             // [0, 512)
        int row = e >> 3, ch = e & 7;
        int r = tb + row;
        r = r < 0 ? 0 : (r > C - 1 ? C - 1 : r);
        size_t so = (size_t)r * 32 + ch * 4;   // u32 units in K plane
        cp16(kh + row * RS + ch * 4, (const u32*)khg + so);
        cp16(kl + row * RS + ch * 4, (const u32*)klg + so);
    }
    // V planes (transposed): 64 d-rows x 64 keys (8 chunks of 8 keys)
#pragma unroll
    for (int t = 0; t < 2; t++) {
        int e = tid + t * 256;             // [0, 512)
        int d = e >> 3, ch = e & 7;
        int k0 = tb + ch * 8;
        k0 = k0 < 0 ? 0 : (k0 > C - 8 ? C - 8 : k0);
        size_t so = ((size_t)d * C + k0) >> 1;  // u32 units in V plane
        cp16(vh + d * RS + ch * 4, (const u32*)vhg + so);
        cp16(vl + d * RS + ch * 4, (const u32*)vlg + so);
    }
    cp_commit();
}

// ---------------- FA2 bf16-split attention ----------------
// CTA = 128 queries x 1 head; 8 warps x 16 rows; m16n8k16 bf16 3-term split.
// 64-key smem tiles processed as two 32-key halves per barrier.

__global__ void __launch_bounds__(256, 2) attn_kernel(
    const float* __restrict__ q, const float* __restrict__ gammas,
    float* __restrict__ out)
{
    extern __shared__ u32 sm[];

    int h = blockIdx.y;
    int qtile = (int)(gridDim.x - 1u - blockIdx.x);   // heavy tiles first
    int qs = qtile * 128;
    int tid = threadIdx.x;
    int warp = tid >> 5, lane = tid & 31;
    int r0 = qs + warp * 16;
    int g = lane >> 2, c = lane & 3;
    int cc = 2 * c;
    int i0 = r0 + g, i1 = i0 + 8;

    // Q split once: qh/ql[ks][0..3] (bf16x2 fragments for 4 k16-steps)
    u32 qh[4][4], ql[4][4];
    {
        const float* q0p = q + ((size_t)h * NN + i0) * DD;
        const float* q1p = q + ((size_t)h * NN + i1) * DD;
#pragma unroll
        for (int ks = 0; ks < 4; ks++) {
            split2(q0p[16 * ks + cc],     q0p[16 * ks + cc + 1], qh[ks][0], ql[ks][0]);
            split2(q1p[16 * ks + cc],     q1p[16 * ks + cc + 1], qh[ks][1], ql[ks][1]);
            split2(q0p[16 * ks + cc + 8], q0p[16 * ks + cc + 9], qh[ks][2], ql[ks][2]);
            split2(q1p[16 * ks + cc + 8], q1p[16 * ks + cc + 9], qh[ks][3], ql[ks][3]);
        }
    }

    float m0 = NEGV, m1 = NEGV, l0 = 0.f, l1 = 0.f;
    float O[8][4];
#pragma unroll
    for (int n = 0; n < 8; n++) { O[n][0] = O[n][1] = O[n][2] = O[n][3] = 0.f; }

    float gm[4] = { __ldg(&gammas[0]), __ldg(&gammas[1]),
                    __ldg(&gammas[2]), __ldg(&gammas[3]) };
    const float scale = 0.125f;

    // one 32-key half: kb/kl offset by half*32*RS rows; vh/vl offset by half*16 words
    auto do_half = [&](const u32* kbh, const u32* kbl, const u32* vbh, const u32* vbl,
                       bool L0, int base, int S, float gamma) {
        float s[4][4];
#pragma unroll
        for (int n = 0; n < 4; n++) { s[n][0] = s[n][1] = s[n][2] = s[n][3] = 0.f; }

        // ---- QK^T: 4 n-steps x 4 k-steps x 3 MMA ----
#pragma unroll
        for (int nb = 0; nb < 4; nb++) {
            const u32* ph = kbh + (nb * 8 + g) * RS + c;
            const u32* pl = kbl + (nb * 8 + g) * RS + c;
#pragma unroll
            for (int ks = 0; ks < 4; ks++) {
                u32 bh0 = ph[8 * ks], bh1 = ph[8 * ks + 4];
                u32 bl0 = pl[8 * ks], bl1 = pl[8 * ks + 4];
                mma_bf16(s[nb][0], s[nb][1], s[nb][2], s[nb][3],
                         qh[ks][0], qh[ks][1], qh[ks][2], qh[ks][3], bh0, bh1);
                mma_bf16(s[nb][0], s[nb][1], s[nb][2], s[nb][3],
                         qh[ks][0], qh[ks][1], qh[ks][2], qh[ks][3], bl0, bl1);
                mma_bf16(s[nb][0], s[nb][1], s[nb][2], s[nb][3],
                         ql[ks][0], ql[ks][1], ql[ks][2], ql[ks][3], bh0, bh1);
            }
        }

        // ---- mask + ALiBi bias ----
#pragma unroll
        for (int n = 0; n < 4; n++) {
            int colA = 8 * n + cc;
            if (L0) {
                int jA = base + colA, jB = jA + 1;
                int dA0 = i0 - jA, dB0 = dA0 - 1;
                int dA1 = dA0 + 8, dB1 = dA1 - 1;
                s[n][0] = (jA >= 0 && (unsigned)dA0 < WW) ? fmaf(s[n][0], scale, -gamma * (float)dA0) : NEGV;
                s[n][1] = (jB >= 0 && (unsigned)dB0 < WW) ? fmaf(s[n][1], scale, -gamma * (float)dB0) : NEGV;
                s[n][2] = (jA >= 0 && (unsigned)dA1 < WW) ? fmaf(s[n][2], scale, -gamma * (float)dA1) : NEGV;
                s[n][3] = (jB >= 0 && (unsigned)dB1 < WW) ? fmaf(s[n][3], scale, -gamma * (float)dB1) : NEGV;
            } else {
                int jlA = (base + colA + 1) * S - 1;
                int jlB = jlA + S;
                int dA0 = i0 - jlA, dB0 = i0 - jlB;
                int dA1 = dA0 + 8, dB1 = dB0 + 8;
                s[n][0] = (dA0 >= WW) ? fmaf(s[n][0], scale, -gamma * (float)dA0) : NEGV;
                s[n][1] = (dB0 >= WW) ? fmaf(s[n][1], scale, -gamma * (float)dB0) : NEGV;
                s[n][2] = (dA1 >= WW) ? fmaf(s[n][2], scale, -gamma * (float)dA1) : NEGV;
                s[n][3] = (dB1 >= WW) ? fmaf(s[n][3], scale, -gamma * (float)dB1) : NEGV;
            }
        }

        // ---- online softmax ----
        float ml0 = s[0][0], ml1 = s[0][2];
#pragma unroll
        for (int n = 0; n < 4; n++) {
            ml0 = fmaxf(ml0, fmaxf(s[n][0], s[n][1]));
            ml1 = fmaxf(ml1, fmaxf(s[n][2], s[n][3]));
        }
        ml0 = fmaxf(ml0, __shfl_xor_sync(0xffffffffu, ml0, 1));
        ml0 = fmaxf(ml0, __shfl_xor_sync(0xffffffffu, ml0, 2));
        ml1 = fmaxf(ml1, __shfl_xor_sync(0xffffffffu, ml1, 1));
        ml1 = fmaxf(ml1, __shfl_xor_sync(0xffffffffu, ml1, 2));
        float nm0 = fmaxf(m0, ml0), nm1 = fmaxf(m1, ml1);
        float e0 = __expf(m0 - nm0), e1 = __expf(m1 - nm1);
        m0 = nm0; m1 = nm1;
        float sum0 = 0.f, sum1 = 0.f;
#pragma unroll
        for (int n = 0; n < 4; n++) {
            s[n][0] = __expf(s[n][0] - nm0); sum0 += s[n][0];
            s[n][1] = __expf(s[n][1] - nm0); sum0 += s[n][1];
            s[n][2] = __expf(s[n][2] - nm1); sum1 += s[n][2];
            s[n][3] = __expf(s[n][3] - nm1); sum1 += s[n][3];
        }
        l0 = fmaf(l0, e0, sum0);
        l1 = fmaf(l1, e1, sum1);
        if (!__all_sync(0xffffffffu, (e0 == 1.f) && (e1 == 1.f))) {
#pragma unroll
            for (int n = 0; n < 8; n++) {
                O[n][0] *= e0; O[n][1] *= e0; O[n][2] *= e1; O[n][3] *= e1;
            }
        }

        // ---- O += P V : 2 k-steps x 8 n-steps x 3 MMA ----
#pragma unroll
        for (int kt = 0; kt < 2; kt++) {
            u32 Ah[4], Al[4];
            split2(s[2 * kt][0],     s[2 * kt][1],     Ah[0], Al[0]);
            split2(s[2 * kt][2],     s[2 * kt][3],     Ah[1], Al[1]);
            split2(s[2 * kt + 1][0], s[2 * kt + 1][1], Ah[2], Al[2]);
            split2(s[2 * kt + 1][2], s[2 * kt + 1][3], Ah[3], Al[3]);
#pragma unroll
            for (int nb = 0; nb < 8; nb++) {
                const u32* ph = vbh + (nb * 8 + g) * RS + c;
                const u32* pl = vbl + (nb * 8 + g) * RS + c;
                u32 bh0 = ph[8 * kt], bh1 = ph[8 * kt + 4];
                u32 bl0 = pl[8 * kt], bl1 = pl[8 * kt + 4];
                mma_bf16(O[nb][0], O[nb][1], O[nb][2], O[nb][3],
                         Ah[0], Ah[1], Ah[2], Ah[3], bh0, bh1);
                mma_bf16(O[nb][0], O[nb][1], O[nb][2], O[nb][3],
                         Ah[0], Ah[1], Ah[2], Ah[3], bl0, bl1);
                mma_bf16(O[nb][0], O[nb][1], O[nb][2], O[nb][3],
                         Al[0], Al[1], Al[2], Al[3], bh0, bh1);
            }
        }
    };

#pragma unroll 1
    for (int lvl = 0; lvl < 4; lvl++) {
        const u16 *khg, *klg, *vhg, *vlg;
        int C, S, n, ntv = 0;
        float gamma = gm[lvl];
        bool L0 = (lvl == 0);
        if (lvl == 0) {
            khg = g_kh0 + (size_t)h * NN * DD;  klg = g_kl0 + (size_t)h * NN * DD;
            vhg = g_vh0 + (size_t)h * DD * NN;  vlg = g_vl0 + (size_t)h * DD * NN;
            C = NN; S = 1;
            n = qs / 64 + 2; if (n > 4) n = 4;       // tiles covering [qs-128, qs+128)
        } else {
            if (lvl == 1) {
                khg = g_kh1 + (size_t)h * 1024 * DD; klg = g_kl1 + (size_t)h * 1024 * DD;
                vhg = g_vh1 + (size_t)h * DD * 1024; vlg = g_vl1 + (size_t)h * DD * 1024;
                C = 1024; S = 8;
            } else if (lvl == 2) {
                khg = g_kh2 + (size_t)h * 128 * DD;  klg = g_kl2 + (size_t)h * 128 * DD;
                vhg = g_vh2 + (size_t)h * DD * 128;  vlg = g_vl2 + (size_t)h * DD * 128;
                C = 128; S = 64;
            } else {
                khg = g_kh3 + (size_t)h * 16 * DD;   klg = g_kl3 + (size_t)h * 16 * DD;
                vhg = g_vh3 + (size_t)h * DD * 16;   vlg = g_vl3 + (size_t)h * DD * 16;
                C = 16; S = 512;
            }
            int cmax = qs / S - 1;
            if (cmax < 0) { continue; }
            ntv = cmax / 64 + 1;
            int dcut = (int)(24.0f / gamma);     // ALiBi horizon (err < e^-20)
            n = 0;
#pragma unroll 1
            for (int it = 0; it < ntv; it++) {
                int cb = (ntv - 1 - it) * 64;
                if (qs - ((cb + 64) * S - 1) <= dcut) n++;
                else break;
            }
            if (n <= 0) continue;
        }

        int cwmax = 0x7fffffff;
        if (!L0) cwmax = (r0 >= 112 + S) ? ((r0 - 112) / S - 1) : -1;
        int dcutw = L0 ? 0 : (int)(24.0f / gamma);

        __syncthreads();            // previous level's buffers done
        int tb0 = L0 ? (qs + 128 - 64) : ((ntv - 1) * 64);
        prefetch64(sm, 0, khg, klg, vhg, vlg, C, tb0, tid);
#pragma unroll 1
        for (int it = 0; it < n; it++) {
            int buf = it & 1;
            int tb = L0 ? (qs + 128 - 64 * (it + 1)) : ((ntv - 1 - it) * 64);
            cp_wait_all();
            __syncthreads();
            if (it + 1 < n) {
                int tb1 = L0 ? (qs + 128 - 64 * (it + 2)) : ((ntv - 2 - it) * 64);
                prefetch64(sm, (it + 1) & 1, khg, klg, vhg, vlg, C, tb1, tid);
            }
            const u32* kb = sm + buf * BUFU;
            const u32* klb = kb + PLANE;
            const u32* vb = klb + PLANE;
            const u32* vlb = vb + PLANE;
            // two 32-key halves, nearest (higher keys) first
#pragma unroll
            for (int hf = 1; hf >= 0; hf--) {
                int base = tb + 32 * hf;
                if (L0) {
                    if (base > r0 + 15 || base + 31 < r0 - (WW - 1)) continue;
                } else {
                    if (base > cwmax) continue;
                    if (r0 - ((base + 32) * S - 1) > dcutw) continue;
                }
                do_half(kb + hf * 32 * RS, klb + hf * 32 * RS,
                        vb + hf * 16, vlb + hf * 16, L0, base, S, gamma);
            }
        }
    }

    // ================= epilogue: out = O / clip(l, 1e-8) =================
    l0 += __shfl_xor_sync(0xffffffffu, l0, 1);
    l0 += __shfl_xor_sync(0xffffffffu, l0, 2);
    l1 += __shfl_xor_sync(0xffffffffu, l1, 1);
    l1 += __shfl_xor_sync(0xffffffffu, l1, 2);
    float inv0 = 1.0f / fmaxf(l0, 1e-8f);
    float inv1 = 1.0f / fmaxf(l1, 1e-8f);
    float* o0p = out + ((size_t)h * NN + i0) * DD;
    float* o1p = out + ((size_t)h * NN + i1) * DD;
#pragma unroll
    for (int n = 0; n < 8; n++) {
        float2 w0 = make_float2(O[n][0] * inv0, O[n][1] * inv0);
        float2 w1 = make_float2(O[n][2] * inv1, O[n][3] * inv1);
        *reinterpret_cast<float2*>(o0p + 8 * n + cc) = w0;
        *reinterpret_cast<float2*>(o1p + 8 * n + cc) = w1;
    }
}

// ---------------- launch ----------------
extern "C" void kernel_launch(void* const* d_in, const int* in_sizes, int n_in,
                              void* d_out, int out_size) {
    const float* q      = (const float*)d_in[0];
    const float* k      = (const float*)d_in[1];
    const float* v      = (const float*)d_in[2];
    const float* gammas = (const float*)d_in[3];
    float* out = (float*)d_out;

    u16 *kh0, *kl0, *vh0, *vl0, *kh1, *kl1, *vh1, *vl1;
    u16 *kh2, *kl2, *vh2, *vl2, *kh3, *kl3, *vh3, *vl3;
    float *k1, *v1, *k2, *v2, *k3, *v3;
    cudaGetSymbolAddress((void**)&kh0, g_kh0); cudaGetSymbolAddress((void**)&kl0, g_kl0);
    cudaGetSymbolAddress((void**)&vh0, g_vh0); cudaGetSymbolAddress((void**)&vl0, g_vl0);
    cudaGetSymbolAddress((void**)&kh1, g_kh1); cudaGetSymbolAddress((void**)&kl1, g_kl1);
    cudaGetSymbolAddress((void**)&vh1, g_vh1); cudaGetSymbolAddress((void**)&vl1, g_vl1);
    cudaGetSymbolAddress((void**)&kh2, g_kh2); cudaGetSymbolAddress((void**)&kl2, g_kl2);
    cudaGetSymbolAddress((void**)&vh2, g_vh2); cudaGetSymbolAddress((void**)&vl2, g_vl2);
    cudaGetSymbolAddress((void**)&kh3, g_kh3); cudaGetSymbolAddress((void**)&kl3, g_kl3);
    cudaGetSymbolAddress((void**)&vh3, g_vh3); cudaGetSymbolAddress((void**)&vl3, g_vl3);
    cudaGetSymbolAddress((void**)&k1, g_k1);   cudaGetSymbolAddress((void**)&v1, g_v1);
    cudaGetSymbolAddress((void**)&k2, g_k2);   cudaGetSymbolAddress((void**)&v2, g_v2);
    cudaGetSymbolAddress((void**)&k3, g_k3);   cudaGetSymbolAddress((void**)&v3, g_v3);

    fuse_kernel<<<dim3(NN / 32, HH), 256>>>(k, v, NN, kh0, kl0, vh0, vl0, k1, v1);
    fuse_kernel<<<dim3(1024 / 32, HH), 256>>>(k1, v1, 1024, kh1, kl1, vh1, vl1, k2, v2);
    fuse_kernel<<<dim3(128 / 32, HH), 256>>>(k2, v2, 128, kh2, kl2, vh2, vl2, k3, v3);
    fuse_kernel<<<dim3(1, HH), 256>>>(k3, v3, 16, kh3, kl3, vh3, vl3, nullptr, nullptr);

    cudaFuncSetAttribute(attn_kernel, cudaFuncAttributeMaxDynamicSharedMemorySize,
                         SMEM_BYTES);
    dim3 grid(NN / 128, HH);
    attn_kernel<<<grid, 256, SMEM_BYTES>>>(q, gammas, out);
}